// round 1
// baseline (speedup 1.0000x reference)
#include <cuda_runtime.h>
#include <cuda_bf16.h>
#include <cstdint>

// Problem constants (fixed by the reference)
#define NNODES 20000
#define NEDGES 200000
#define D_IN   1433
#define D_H1   1000
#define D_H2   500
#define D_OUT  7

// ---------------------------------------------------------------------------
// Scratch (device globals; no dynamic allocation allowed)
// ---------------------------------------------------------------------------
__device__ float g_t1[(size_t)NNODES * D_H1];   // features @ W1
__device__ float g_x1[(size_t)NNODES * D_H1];   // relu(agg(t1)+b1)
__device__ float g_t2[(size_t)NNODES * D_H2];   // x1 @ W2
__device__ float g_x2[(size_t)NNODES * D_H2];   // relu(agg(t2)+b2)
__device__ int   g_count[NNODES];
__device__ int   g_pos[NNODES];
__device__ int   g_offs[NNODES + 1];
__device__ int   g_eidx[NEDGES];                // src ids grouped by dst

// ---------------------------------------------------------------------------
// f32x2 packed-FMA helpers (doubles fp32 FMA throughput on sm_103a)
// ---------------------------------------------------------------------------
using u64 = unsigned long long;

__device__ __forceinline__ u64 fma2(u64 a, u64 b, u64 c) {
    u64 d;
    asm("fma.rn.f32x2 %0, %1, %2, %3;" : "=l"(d) : "l"(a), "l"(b), "l"(c));
    return d;
}
__device__ __forceinline__ u64 pack2(float lo, float hi) {
    u64 d;
    asm("mov.b64 %0, {%1, %2};" : "=l"(d) : "f"(lo), "f"(hi));
    return d;
}
__device__ __forceinline__ void unpack2(u64 v, float& lo, float& hi) {
    asm("mov.b64 {%0, %1}, %2;" : "=f"(lo), "=f"(hi) : "l"(v));
}

// ---------------------------------------------------------------------------
// CSR build
// ---------------------------------------------------------------------------
__global__ void zero_counts_kernel() {
    int i = blockIdx.x * blockDim.x + threadIdx.x;
    if (i < NNODES) { g_count[i] = 0; g_pos[i] = 0; }
}

__global__ void count_kernel(const int* __restrict__ dst) {
    int e = blockIdx.x * blockDim.x + threadIdx.x;
    if (e < NEDGES) atomicAdd(&g_count[dst[e]], 1);
}

// Single-block exclusive scan of g_count -> g_offs (20001 entries)
__global__ void scan_kernel() {
    __shared__ int part[1024];
    const int tid = threadIdx.x;
    const int CH = (NNODES + 1023) / 1024;  // 20
    const int base = tid * CH;
    int s = 0;
    for (int i = 0; i < CH; ++i) {
        int idx = base + i;
        if (idx < NNODES) s += g_count[idx];
    }
    part[tid] = s;
    __syncthreads();
    for (int off = 1; off < 1024; off <<= 1) {
        int v = (tid >= off) ? part[tid - off] : 0;
        __syncthreads();
        part[tid] += v;
        __syncthreads();
    }
    int run = part[tid] - s;  // exclusive prefix for this chunk
    for (int i = 0; i < CH; ++i) {
        int idx = base + i;
        if (idx < NNODES) { g_offs[idx] = run; run += g_count[idx]; }
    }
    if (tid == 1023) g_offs[NNODES] = part[1023];
}

__global__ void fill_kernel(const int* __restrict__ src, const int* __restrict__ dst) {
    int e = blockIdx.x * blockDim.x + threadIdx.x;
    if (e < NEDGES) {
        int d = dst[e];
        int p = atomicAdd(&g_pos[d], 1);
        g_eidx[g_offs[d] + p] = src[e];
    }
}

// ---------------------------------------------------------------------------
// SGEMM: C[M,N] = A[M,K] @ B[K,N], row-major, fp32 via f32x2 FMA
// BM=128, BN=128, BK=16, 256 threads, 8x8 register tile per thread
// ---------------------------------------------------------------------------
#define BM 128
#define BN 128
#define BK 16
#define TM 8
#define TN 8

__global__ __launch_bounds__(256, 2)
void sgemm_kernel(const float* __restrict__ A, const float* __restrict__ B,
                  float* __restrict__ C, int M, int N, int K) {
    __shared__ float As[BK][BM];   // transposed: As[k][m]
    __shared__ float Bs[BK][BN];

    const int tx = threadIdx.x;            // 0..255
    const int block_row = blockIdx.y * BM;
    const int block_col = blockIdx.x * BN;
    const int tcol = (tx % (BN / TN)) * TN;   // 0,8,...,120
    const int trow = (tx / (BN / TN)) * TM;

    u64 acc[TM][TN / 2];
#pragma unroll
    for (int i = 0; i < TM; ++i)
#pragma unroll
        for (int j = 0; j < TN / 2; ++j) acc[i][j] = 0ull;

    for (int k0 = 0; k0 < K; k0 += BK) {
        // Load A tile (BM x BK) into As transposed
#pragma unroll
        for (int it = 0; it < (BM * BK) / 256; ++it) {
            int i = tx + it * 256;
            int r = i / BK, c = i % BK;
            int gr = block_row + r, gc = k0 + c;
            As[c][r] = (gr < M && gc < K) ? A[(size_t)gr * K + gc] : 0.f;
        }
        // Load B tile (BK x BN)
#pragma unroll
        for (int it = 0; it < (BK * BN) / 256; ++it) {
            int i = tx + it * 256;
            int r = i / BN, c = i % BN;
            int gr = k0 + r, gc = block_col + c;
            Bs[r][c] = (gr < K && gc < N) ? B[(size_t)gr * N + gc] : 0.f;
        }
        __syncthreads();

#pragma unroll
        for (int kk = 0; kk < BK; ++kk) {
            float4 a0 = *reinterpret_cast<const float4*>(&As[kk][trow]);
            float4 a1 = *reinterpret_cast<const float4*>(&As[kk][trow + 4]);
            const u64* bp = reinterpret_cast<const u64*>(&Bs[kk][tcol]);
            u64 brp[4];
#pragma unroll
            for (int j = 0; j < 4; ++j) brp[j] = bp[j];

            float av[8] = {a0.x, a0.y, a0.z, a0.w, a1.x, a1.y, a1.z, a1.w};
#pragma unroll
            for (int i = 0; i < TM; ++i) {
                u64 ap = pack2(av[i], av[i]);
#pragma unroll
                for (int j = 0; j < TN / 2; ++j)
                    acc[i][j] = fma2(ap, brp[j], acc[i][j]);
            }
        }
        __syncthreads();
    }

    // Epilogue: plain store (bias/relu applied after aggregation elsewhere)
#pragma unroll
    for (int i = 0; i < TM; ++i) {
        int gr = block_row + trow + i;
        if (gr >= M) continue;
#pragma unroll
        for (int j = 0; j < TN / 2; ++j) {
            float lo, hi;
            unpack2(acc[i][j], lo, hi);
            int gc = block_col + tcol + 2 * j;
            if (gc < N)     C[(size_t)gr * N + gc] = lo;
            if (gc + 1 < N) C[(size_t)gr * N + gc + 1] = hi;
        }
    }
}

// ---------------------------------------------------------------------------
// Aggregation + bias + relu: out[i,:] = relu(bias + sum_{j in CSR(i)} t[j,:])
// One CTA per destination node.
// ---------------------------------------------------------------------------
__global__ void agg_bias_relu_kernel(const float* __restrict__ t,
                                     const float* __restrict__ bias,
                                     float* __restrict__ out, int D) {
    __shared__ int nbr[512];
    const int node = blockIdx.x;
    const int beg = g_offs[node], end = g_offs[node + 1];
    const int deg = end - beg;

    const int* elist;
    if (deg <= 512) {
        for (int i = threadIdx.x; i < deg; i += blockDim.x) nbr[i] = g_eidx[beg + i];
        __syncthreads();
        elist = nbr;
    } else {
        elist = g_eidx + beg;   // extremely unlikely fallback
    }

    for (int d = threadIdx.x; d < D; d += blockDim.x) {
        float acc = bias[d];
        for (int e = 0; e < deg; ++e) {
            int s = elist[e];
            acc += t[(size_t)s * D + d];
        }
        out[(size_t)node * D + d] = fmaxf(acc, 0.f);
    }
}

// ---------------------------------------------------------------------------
// Output layer: out[i,:7] = relu(x2[i,:] @ W3 + b3), one warp per row
// ---------------------------------------------------------------------------
__global__ void out_layer_kernel(const float* __restrict__ x2,
                                 const float* __restrict__ W3,
                                 const float* __restrict__ b3,
                                 float* __restrict__ out) {
    __shared__ float Ws[D_H2 * D_OUT];
    for (int i = threadIdx.x; i < D_H2 * D_OUT; i += blockDim.x) Ws[i] = W3[i];
    __syncthreads();

    const int warp = (blockIdx.x * blockDim.x + threadIdx.x) >> 5;
    const int lane = threadIdx.x & 31;
    if (warp >= NNODES) return;

    float acc[D_OUT] = {0.f, 0.f, 0.f, 0.f, 0.f, 0.f, 0.f};
    const float* row = x2 + (size_t)warp * D_H2;
    for (int k = lane; k < D_H2; k += 32) {
        float v = row[k];
#pragma unroll
        for (int j = 0; j < D_OUT; ++j) acc[j] += v * Ws[k * D_OUT + j];
    }
#pragma unroll
    for (int j = 0; j < D_OUT; ++j) {
#pragma unroll
        for (int off = 16; off > 0; off >>= 1)
            acc[j] += __shfl_xor_sync(0xFFFFFFFFu, acc[j], off);
    }
    if (lane == 0) {
#pragma unroll
        for (int j = 0; j < D_OUT; ++j)
            out[(size_t)warp * D_OUT + j] = fmaxf(acc[j] + b3[j], 0.f);
    }
}

// ---------------------------------------------------------------------------
// Launch
// ---------------------------------------------------------------------------
extern "C" void kernel_launch(void* const* d_in, const int* in_sizes, int n_in,
                              void* d_out, int out_size) {
    const float* features = (const float*)d_in[0];
    const int*   src      = (const int*)  d_in[1];
    const int*   dst      = (const int*)  d_in[2];
    const float* W1       = (const float*)d_in[3];
    const float* b1       = (const float*)d_in[4];
    const float* W2       = (const float*)d_in[5];
    const float* b2       = (const float*)d_in[6];
    const float* W3       = (const float*)d_in[7];
    const float* b3       = (const float*)d_in[8];
    float* out = (float*)d_out;

    // Raw pointers to device globals (usable directly in kernels; we pass
    // the big scratch buffers explicitly for clarity)
    float *t1, *x1, *t2, *x2;
    cudaGetSymbolAddress((void**)&t1, g_t1);
    cudaGetSymbolAddress((void**)&x1, g_x1);
    cudaGetSymbolAddress((void**)&t2, g_t2);
    cudaGetSymbolAddress((void**)&x2, g_x2);

    // --- CSR build (per call; graph-capturable, deterministic workload) ---
    zero_counts_kernel<<<(NNODES + 255) / 256, 256>>>();
    count_kernel<<<(NEDGES + 255) / 256, 256>>>(dst);
    scan_kernel<<<1, 1024>>>();
    fill_kernel<<<(NEDGES + 255) / 256, 256>>>(src, dst);

    // --- Layer 1: t1 = features @ W1 ; x1 = relu(agg(t1) + b1) ---
    {
        dim3 grid((D_H1 + BN - 1) / BN, (NNODES + BM - 1) / BM);
        sgemm_kernel<<<grid, 256>>>(features, W1, t1, NNODES, D_H1, D_IN);
        agg_bias_relu_kernel<<<NNODES, 256>>>(t1, b1, x1, D_H1);
    }

    // --- Layer 2: t2 = x1 @ W2 ; x2 = relu(agg(t2) + b2) ---
    {
        dim3 grid((D_H2 + BN - 1) / BN, (NNODES + BM - 1) / BM);
        sgemm_kernel<<<grid, 256>>>(x1, W2, t2, NNODES, D_H2, D_H1);
        agg_bias_relu_kernel<<<NNODES, 256>>>(t2, b2, x2, D_H2);
    }

    // --- Output layer: out = relu(x2 @ W3 + b3) ---
    {
        int warps_per_block = 256 / 32;
        int blocks = (NNODES + warps_per_block - 1) / warps_per_block;
        out_layer_kernel<<<blocks, 256>>>(x2, W3, b3, out);
    }
}

// round 3
// speedup vs baseline: 2.3131x; 2.3131x over previous
#include <cuda_runtime.h>
#include <cuda_bf16.h>
#include <cstdint>

// Problem constants
#define NNODES 20000
#define NEDGES 200000
#define D_IN   1433
#define D_H1   1000
#define D_H2   500
#define D_OUT  7

// Padded GEMM dims
#define K1PAD  1472   // >= 1433, mult of 32
#define K2PAD  1024   // >= 1000, mult of 32
#define N1PAD  1024   // >= 1000, mult of 128
#define N2PAD  512    // >= 500,  mult of 128

// ---------------------------------------------------------------------------
// Device scratch
// ---------------------------------------------------------------------------
__device__ __align__(256) __nv_bfloat16 g_fa_hi[(size_t)NNODES * K1PAD];
__device__ __align__(256) __nv_bfloat16 g_fa_lo[(size_t)NNODES * K1PAD];
__device__ __align__(256) __nv_bfloat16 g_w1t_hi[(size_t)N1PAD * K1PAD];
__device__ __align__(256) __nv_bfloat16 g_w1t_lo[(size_t)N1PAD * K1PAD];
__device__ __align__(256) __nv_bfloat16 g_x1_hi[(size_t)NNODES * K2PAD];
__device__ __align__(256) __nv_bfloat16 g_x1_lo[(size_t)NNODES * K2PAD];
__device__ __align__(256) __nv_bfloat16 g_w2t_hi[(size_t)N2PAD * K2PAD];
__device__ __align__(256) __nv_bfloat16 g_w2t_lo[(size_t)N2PAD * K2PAD];
__device__ __align__(256) float g_t1[(size_t)NNODES * D_H1];
__device__ __align__(256) float g_t2[(size_t)NNODES * D_H2];
__device__ __align__(256) float g_x2[(size_t)NNODES * D_H2];
__device__ int g_count[NNODES];
__device__ int g_pos[NNODES];
__device__ int g_offs[NNODES + 1];
__device__ int g_eidx[NEDGES];

// ---------------------------------------------------------------------------
// PTX helpers (portable ISA only: ldmatrix / mma.sync / cp.async)
// ---------------------------------------------------------------------------
__device__ __forceinline__ uint32_t smem_to_u32(const void* p) {
    uint32_t a;
    asm("{ .reg .u64 t; cvta.to.shared.u64 t, %1; cvt.u32.u64 %0, t; }"
        : "=r"(a) : "l"(p));
    return a;
}

__device__ __forceinline__ void cp_async16(uint32_t sdst, const void* gsrc, bool ok) {
    int sz = ok ? 16 : 0;
    asm volatile("cp.async.cg.shared.global [%0], [%1], 16, %2;\n"
                 :: "r"(sdst), "l"(gsrc), "r"(sz));
}
#define CP_COMMIT() asm volatile("cp.async.commit_group;\n" ::: "memory")
#define CP_WAIT(n)  asm volatile("cp.async.wait_group %0;\n" :: "n"(n) : "memory")

__device__ __forceinline__ void ldm_x4(uint32_t& r0, uint32_t& r1, uint32_t& r2,
                                       uint32_t& r3, uint32_t addr) {
    asm volatile("ldmatrix.sync.aligned.m8n8.x4.shared.b16 {%0,%1,%2,%3}, [%4];"
                 : "=r"(r0), "=r"(r1), "=r"(r2), "=r"(r3) : "r"(addr));
}

__device__ __forceinline__ void mma_bf16(float* c, const uint32_t* a, const uint32_t* b) {
    asm volatile(
        "mma.sync.aligned.m16n8k16.row.col.f32.bf16.bf16.f32 "
        "{%0,%1,%2,%3}, {%4,%5,%6,%7}, {%8,%9}, {%0,%1,%2,%3};"
        : "+f"(c[0]), "+f"(c[1]), "+f"(c[2]), "+f"(c[3])
        : "r"(a[0]), "r"(a[1]), "r"(a[2]), "r"(a[3]), "r"(b[0]), "r"(b[1]));
}

// ---------------------------------------------------------------------------
// CSR build
// ---------------------------------------------------------------------------
__global__ void zero_counts_kernel() {
    int i = blockIdx.x * blockDim.x + threadIdx.x;
    if (i < NNODES) { g_count[i] = 0; g_pos[i] = 0; }
}
__global__ void count_kernel(const int* __restrict__ dst) {
    int e = blockIdx.x * blockDim.x + threadIdx.x;
    if (e < NEDGES) atomicAdd(&g_count[dst[e]], 1);
}
__global__ void scan_kernel() {
    __shared__ int part[1024];
    const int tid = threadIdx.x;
    const int CH = (NNODES + 1023) / 1024;
    const int base = tid * CH;
    int s = 0;
    for (int i = 0; i < CH; ++i) {
        int idx = base + i;
        if (idx < NNODES) s += g_count[idx];
    }
    part[tid] = s;
    __syncthreads();
    for (int off = 1; off < 1024; off <<= 1) {
        int v = (tid >= off) ? part[tid - off] : 0;
        __syncthreads();
        part[tid] += v;
        __syncthreads();
    }
    int run = part[tid] - s;
    for (int i = 0; i < CH; ++i) {
        int idx = base + i;
        if (idx < NNODES) { g_offs[idx] = run; run += g_count[idx]; }
    }
    if (tid == 1023) g_offs[NNODES] = part[1023];
}
__global__ void fill_kernel(const int* __restrict__ src, const int* __restrict__ dst) {
    int e = blockIdx.x * blockDim.x + threadIdx.x;
    if (e < NEDGES) {
        int d = dst[e];
        int p = atomicAdd(&g_pos[d], 1);
        g_eidx[g_offs[d] + p] = src[e];
    }
}

// ---------------------------------------------------------------------------
// Conversion kernels: fp32 -> (bf16 hi, bf16 lo), zero-padded
// ---------------------------------------------------------------------------
__global__ void split_pad_kernel(const float* __restrict__ src,
                                 __nv_bfloat16* __restrict__ hi,
                                 __nv_bfloat16* __restrict__ lo,
                                 int M, int K, int Kpad) {
    size_t idx = (size_t)blockIdx.x * blockDim.x + threadIdx.x;
    size_t total = (size_t)M * Kpad;
    if (idx >= total) return;
    int r = (int)(idx / Kpad);
    int c = (int)(idx % Kpad);
    float x = (c < K) ? src[(size_t)r * K + c] : 0.f;
    __nv_bfloat16 h = __float2bfloat16(x);
    float res = x - __bfloat162float(h);
    hi[idx] = h;
    lo[idx] = __float2bfloat16(res);
}

// W [K,N] row-major -> Wt hi/lo [Npad][Kpad] (K-major rows), zero-padded
__global__ void transpose_split_kernel(const float* __restrict__ W,
                                       __nv_bfloat16* __restrict__ thi,
                                       __nv_bfloat16* __restrict__ tlo,
                                       int K, int N, int Kpad, int Npad) {
    size_t idx = (size_t)blockIdx.x * blockDim.x + threadIdx.x;
    size_t total = (size_t)Npad * Kpad;
    if (idx >= total) return;
    int n = (int)(idx / Kpad);
    int k = (int)(idx % Kpad);
    float x = (n < N && k < K) ? W[(size_t)k * N + n] : 0.f;
    __nv_bfloat16 h = __float2bfloat16(x);
    float res = x - __bfloat162float(h);
    thi[idx] = h;
    tlo[idx] = __float2bfloat16(res);
}

// ---------------------------------------------------------------------------
// HMMA GEMM (mma.sync m16n8k16 bf16, fp32 accum):
//   C[M, Nreal] = Ahi@Bhi^T + Alo@Bhi^T + Ahi@Blo^T
// A*: [M x Kpad] bf16 K-major. B*: [Npad x Kpad] bf16 K-major.
// CTA tile 128x128, BK=32, 8 warps (4m x 2n), warp tile 32x64.
// Double-buffered cp.async. SMEM rows padded to 40 halves (conflict-free ldmatrix).
// ---------------------------------------------------------------------------
#define BK 32
#define ROW_H 40                              // halves per smem row (32 + 8 pad)
#define TILE_H (128 * ROW_H)                  // halves per tile
#define A_LO_OFF ((uint32_t)(TILE_H * 2))     // byte offsets within a stage
#define B_HI_OFF ((uint32_t)(TILE_H * 4))
#define B_LO_OFF ((uint32_t)(TILE_H * 6))
#define STAGE_BYTES ((uint32_t)(TILE_H * 8))  // 40960 B
#define GEMM_SMEM (2 * STAGE_BYTES)           // 81920 B

__global__ __launch_bounds__(256, 1)
void hmma_gemm3_kernel(const __nv_bfloat16* __restrict__ a_hi,
                       const __nv_bfloat16* __restrict__ a_lo,
                       const __nv_bfloat16* __restrict__ b_hi,
                       const __nv_bfloat16* __restrict__ b_lo,
                       float* __restrict__ C,
                       int M, int Nreal, int Kpad) {
    extern __shared__ __nv_bfloat16 smem[];
    const uint32_t smem_u32 = smem_to_u32(smem);
    const int t = threadIdx.x;
    const int lane = t & 31;
    const int wid = t >> 5;
    const int wm = wid & 3;          // warp m index (0..3) -> rows wm*32
    const int wn = wid >> 2;         // warp n index (0..1) -> cols wn*64
    const int m0 = blockIdx.y * 128;
    const int n0 = blockIdx.x * 128;
    const int nchunk = Kpad / BK;

    float acc[2][8][4];
#pragma unroll
    for (int i = 0; i < 2; ++i)
#pragma unroll
        for (int j = 0; j < 8; ++j)
#pragma unroll
            for (int k = 0; k < 4; ++k) acc[i][j][k] = 0.f;

    // ---- stage loader ----
    auto load_stage = [&](int c) {
        const int s = c & 1;
        const int k0 = c * BK;
        const uint32_t sbase = smem_u32 + s * STAGE_BYTES;
#pragma unroll
        for (int i = 0; i < 2; ++i) {
            int idx = t + i * 256;          // 0..511
            int row = idx >> 2;             // 0..127
            int ch = idx & 3;               // 16B chunk (8 halves)
            uint32_t dst = sbase + (uint32_t)(row * ROW_H + ch * 8) * 2;
            int gm = m0 + row;
            bool ok = gm < M;
            int gmc = ok ? gm : (M - 1);
            size_t goa = (size_t)gmc * Kpad + k0 + ch * 8;
            cp_async16(dst, a_hi + goa, ok);
            cp_async16(dst + A_LO_OFF, a_lo + goa, ok);
            size_t gob = (size_t)(n0 + row) * Kpad + k0 + ch * 8;
            cp_async16(dst + B_HI_OFF, b_hi + gob, true);
            cp_async16(dst + B_LO_OFF, b_lo + gob, true);
        }
        CP_COMMIT();
    };

    load_stage(0);

    for (int c = 0; c < nchunk; ++c) {
        if (c + 1 < nchunk) {
            load_stage(c + 1);
            CP_WAIT(1);
        } else {
            CP_WAIT(0);
        }
        __syncthreads();

        const uint32_t sb = smem_u32 + (uint32_t)(c & 1) * STAGE_BYTES;
#pragma unroll
        for (int ks = 0; ks < 2; ++ks) {
            const int k0s = ks * 16;
            // A fragments (2 m-tiles x {hi,lo})
            uint32_t afh[2][4], afl[2][4];
            {
                int ar = (lane & 7) + ((lane >> 3) & 1) * 8;  // row within 16
                int ak = k0s + (lane >> 4) * 8;
#pragma unroll
                for (int mt = 0; mt < 2; ++mt) {
                    uint32_t addr = sb +
                        (uint32_t)((wm * 32 + mt * 16 + ar) * ROW_H + ak) * 2;
                    ldm_x4(afh[mt][0], afh[mt][1], afh[mt][2], afh[mt][3], addr);
                    ldm_x4(afl[mt][0], afl[mt][1], afl[mt][2], afl[mt][3],
                           addr + A_LO_OFF);
                }
            }
            // B fragments (8 n8-tiles x {hi,lo}), loaded as 4 groups of 16 n's
            uint32_t bfh[8][2], bfl[8][2];
            {
                int brr = (lane & 7) + (lane >> 4) * 8;       // n row within 16
                int bk = k0s + ((lane >> 3) & 1) * 8;
#pragma unroll
                for (int ng = 0; ng < 4; ++ng) {
                    uint32_t addr = sb + B_HI_OFF +
                        (uint32_t)((wn * 64 + ng * 16 + brr) * ROW_H + bk) * 2;
                    uint32_t r0, r1, r2, r3;
                    ldm_x4(r0, r1, r2, r3, addr);
                    bfh[2 * ng][0] = r0; bfh[2 * ng][1] = r1;
                    bfh[2 * ng + 1][0] = r2; bfh[2 * ng + 1][1] = r3;
                    ldm_x4(r0, r1, r2, r3, addr + (B_LO_OFF - B_HI_OFF));
                    bfl[2 * ng][0] = r0; bfl[2 * ng][1] = r1;
                    bfl[2 * ng + 1][0] = r2; bfl[2 * ng + 1][1] = r3;
                }
            }
            // 3-pass MMAs
#pragma unroll
            for (int mt = 0; mt < 2; ++mt) {
#pragma unroll
                for (int nt = 0; nt < 8; ++nt) {
                    mma_bf16(acc[mt][nt], afh[mt], bfh[nt]);
                    mma_bf16(acc[mt][nt], afl[mt], bfh[nt]);
                    mma_bf16(acc[mt][nt], afh[mt], bfl[nt]);
                }
            }
        }
        __syncthreads();
    }

    // ---- epilogue: direct float2 stores ----
#pragma unroll
    for (int mt = 0; mt < 2; ++mt) {
        int gr0 = m0 + wm * 32 + mt * 16 + (lane >> 2);
#pragma unroll
        for (int nt = 0; nt < 8; ++nt) {
            int gc = n0 + wn * 64 + nt * 8 + (lane & 3) * 2;
            if (gc >= Nreal) continue;
            if (gr0 < M) {
                float2 v = make_float2(acc[mt][nt][0], acc[mt][nt][1]);
                *reinterpret_cast<float2*>(&C[(size_t)gr0 * Nreal + gc]) = v;
            }
            if (gr0 + 8 < M) {
                float2 v = make_float2(acc[mt][nt][2], acc[mt][nt][3]);
                *reinterpret_cast<float2*>(&C[(size_t)(gr0 + 8) * Nreal + gc]) = v;
            }
        }
    }
}

// ---------------------------------------------------------------------------
// Aggregation + bias + relu (+ bf16 hi/lo split variant for next GEMM input)
// ---------------------------------------------------------------------------
__global__ void agg_bias_relu_split_kernel(const float* __restrict__ t,
                                           const float* __restrict__ bias,
                                           __nv_bfloat16* __restrict__ xhi,
                                           __nv_bfloat16* __restrict__ xlo) {
    __shared__ int nbr[512];
    const int node = blockIdx.x;
    const int beg = g_offs[node], end = g_offs[node + 1];
    const int deg = end - beg;
    const int* elist;
    if (deg <= 512) {
        for (int i = threadIdx.x; i < deg; i += blockDim.x) nbr[i] = g_eidx[beg + i];
        __syncthreads();
        elist = nbr;
    } else {
        elist = g_eidx + beg;
    }
    for (int d = threadIdx.x; d < K2PAD; d += blockDim.x) {
        float y = 0.f;
        if (d < D_H1) {
            float acc = bias[d];
            for (int e = 0; e < deg; ++e)
                acc += t[(size_t)elist[e] * D_H1 + d];
            y = fmaxf(acc, 0.f);
        }
        __nv_bfloat16 h = __float2bfloat16(y);
        float res = y - __bfloat162float(h);
        size_t o = (size_t)node * K2PAD + d;
        xhi[o] = h;
        xlo[o] = __float2bfloat16(res);
    }
}

__global__ void agg_bias_relu_kernel(const float* __restrict__ t,
                                     const float* __restrict__ bias,
                                     float* __restrict__ out, int D) {
    __shared__ int nbr[512];
    const int node = blockIdx.x;
    const int beg = g_offs[node], end = g_offs[node + 1];
    const int deg = end - beg;
    const int* elist;
    if (deg <= 512) {
        for (int i = threadIdx.x; i < deg; i += blockDim.x) nbr[i] = g_eidx[beg + i];
        __syncthreads();
        elist = nbr;
    } else {
        elist = g_eidx + beg;
    }
    for (int d = threadIdx.x; d < D; d += blockDim.x) {
        float acc = bias[d];
        for (int e = 0; e < deg; ++e)
            acc += t[(size_t)elist[e] * D + d];
        out[(size_t)node * D + d] = fmaxf(acc, 0.f);
    }
}

// ---------------------------------------------------------------------------
// Output layer: out[i,:7] = relu(x2[i,:] @ W3 + b3), one warp per row
// ---------------------------------------------------------------------------
__global__ void out_layer_kernel(const float* __restrict__ x2,
                                 const float* __restrict__ W3,
                                 const float* __restrict__ b3,
                                 float* __restrict__ out) {
    __shared__ float Ws[D_H2 * D_OUT];
    for (int i = threadIdx.x; i < D_H2 * D_OUT; i += blockDim.x) Ws[i] = W3[i];
    __syncthreads();
    const int warp = (blockIdx.x * blockDim.x + threadIdx.x) >> 5;
    const int lane = threadIdx.x & 31;
    if (warp >= NNODES) return;
    float acc[D_OUT] = {0.f, 0.f, 0.f, 0.f, 0.f, 0.f, 0.f};
    const float* row = x2 + (size_t)warp * D_H2;
    for (int k = lane; k < D_H2; k += 32) {
        float v = row[k];
#pragma unroll
        for (int j = 0; j < D_OUT; ++j) acc[j] += v * Ws[k * D_OUT + j];
    }
#pragma unroll
    for (int j = 0; j < D_OUT; ++j) {
#pragma unroll
        for (int off = 16; off > 0; off >>= 1)
            acc[j] += __shfl_xor_sync(0xFFFFFFFFu, acc[j], off);
    }
    if (lane == 0) {
#pragma unroll
        for (int j = 0; j < D_OUT; ++j)
            out[(size_t)warp * D_OUT + j] = fmaxf(acc[j] + b3[j], 0.f);
    }
}

// ---------------------------------------------------------------------------
// Launch
// ---------------------------------------------------------------------------
extern "C" void kernel_launch(void* const* d_in, const int* in_sizes, int n_in,
                              void* d_out, int out_size) {
    const float* features = (const float*)d_in[0];
    const int*   src      = (const int*)  d_in[1];
    const int*   dst      = (const int*)  d_in[2];
    const float* W1       = (const float*)d_in[3];
    const float* b1       = (const float*)d_in[4];
    const float* W2       = (const float*)d_in[5];
    const float* b2       = (const float*)d_in[6];
    const float* W3       = (const float*)d_in[7];
    const float* b3       = (const float*)d_in[8];
    float* out = (float*)d_out;

    __nv_bfloat16 *fa_hi, *fa_lo, *w1t_hi, *w1t_lo, *x1_hi, *x1_lo, *w2t_hi, *w2t_lo;
    float *t1, *t2, *x2;
    cudaGetSymbolAddress((void**)&fa_hi, g_fa_hi);
    cudaGetSymbolAddress((void**)&fa_lo, g_fa_lo);
    cudaGetSymbolAddress((void**)&w1t_hi, g_w1t_hi);
    cudaGetSymbolAddress((void**)&w1t_lo, g_w1t_lo);
    cudaGetSymbolAddress((void**)&x1_hi, g_x1_hi);
    cudaGetSymbolAddress((void**)&x1_lo, g_x1_lo);
    cudaGetSymbolAddress((void**)&w2t_hi, g_w2t_hi);
    cudaGetSymbolAddress((void**)&w2t_lo, g_w2t_lo);
    cudaGetSymbolAddress((void**)&t1, g_t1);
    cudaGetSymbolAddress((void**)&t2, g_t2);
    cudaGetSymbolAddress((void**)&x2, g_x2);

    cudaFuncSetAttribute(hmma_gemm3_kernel,
                         cudaFuncAttributeMaxDynamicSharedMemorySize, GEMM_SMEM);

    // CSR build
    zero_counts_kernel<<<(NNODES + 255) / 256, 256>>>();
    count_kernel<<<(NEDGES + 255) / 256, 256>>>(dst);
    scan_kernel<<<1, 1024>>>();
    fill_kernel<<<(NEDGES + 255) / 256, 256>>>(src, dst);

    // Conversions
    {
        size_t tot = (size_t)NNODES * K1PAD;
        split_pad_kernel<<<(unsigned)((tot + 255) / 256), 256>>>(
            features, fa_hi, fa_lo, NNODES, D_IN, K1PAD);
        size_t wt = (size_t)N1PAD * K1PAD;
        transpose_split_kernel<<<(unsigned)((wt + 255) / 256), 256>>>(
            W1, w1t_hi, w1t_lo, D_IN, D_H1, K1PAD, N1PAD);
        size_t wt2 = (size_t)N2PAD * K2PAD;
        transpose_split_kernel<<<(unsigned)((wt2 + 255) / 256), 256>>>(
            W2, w2t_hi, w2t_lo, D_H1, D_H2, K2PAD, N2PAD);
    }

    // Layer 1: t1 = features @ W1 ; x1 = relu(agg(t1)+b1), split to bf16 hi/lo
    {
        dim3 grid(N1PAD / 128, (NNODES + 127) / 128);
        hmma_gemm3_kernel<<<grid, 256, GEMM_SMEM>>>(fa_hi, fa_lo, w1t_hi, w1t_lo,
                                                    t1, NNODES, D_H1, K1PAD);
        agg_bias_relu_split_kernel<<<NNODES, 256>>>(t1, b1, x1_hi, x1_lo);
    }

    // Layer 2: t2 = x1 @ W2 ; x2 = relu(agg(t2)+b2)
    {
        dim3 grid(N2PAD / 128, (NNODES + 127) / 128);
        hmma_gemm3_kernel<<<grid, 256, GEMM_SMEM>>>(x1_hi, x1_lo, w2t_hi, w2t_lo,
                                                    t2, NNODES, D_H2, K2PAD);
        agg_bias_relu_kernel<<<NNODES, 256>>>(t2, b2, x2, D_H2);
    }

    // Output layer
    {
        int blocks = (NNODES + 7) / 8;
        out_layer_kernel<<<blocks, 256>>>(x2, W3, b3, out);
    }
}

// round 4
// speedup vs baseline: 3.0607x; 1.3232x over previous
#include <cuda_runtime.h>
#include <cuda_bf16.h>
#include <cstdint>

// Problem constants
#define NNODES 20000
#define NEDGES 200000
#define D_IN   1433
#define D_H1   1000
#define D_H2   500
#define D_OUT  7

// Padded GEMM dims
#define K1PAD  1472   // >= 1433, mult of 64
#define K2PAD  1024   // >= 1000, mult of 64
#define N1PAD  1024   // >= 1000, mult of 128
#define N2PAD  512    // >= 500,  mult of 128

// ---------------------------------------------------------------------------
// Device scratch
// ---------------------------------------------------------------------------
__device__ __align__(256) __nv_bfloat16 g_fa_hi[(size_t)NNODES * K1PAD];
__device__ __align__(256) __nv_bfloat16 g_fa_lo[(size_t)NNODES * K1PAD];
__device__ __align__(256) __nv_bfloat16 g_w1t_hi[(size_t)N1PAD * K1PAD];
__device__ __align__(256) __nv_bfloat16 g_w1t_lo[(size_t)N1PAD * K1PAD];
__device__ __align__(256) __nv_bfloat16 g_x1_hi[(size_t)NNODES * K2PAD];
__device__ __align__(256) __nv_bfloat16 g_x1_lo[(size_t)NNODES * K2PAD];
__device__ __align__(256) __nv_bfloat16 g_w2t_hi[(size_t)N2PAD * K2PAD];
__device__ __align__(256) __nv_bfloat16 g_w2t_lo[(size_t)N2PAD * K2PAD];
__device__ __align__(256) float g_t1[(size_t)NNODES * D_H1];
__device__ __align__(256) float g_t2[(size_t)NNODES * D_H2];
__device__ __align__(256) float g_x2[(size_t)NNODES * D_H2];
__device__ int g_count[NNODES];
__device__ int g_pos[NNODES];
__device__ int g_offs[NNODES + 1];
__device__ int g_eidx[NEDGES];

// ---------------------------------------------------------------------------
// PTX helpers (portable ISA: ldmatrix / mma.sync / cp.async)
// ---------------------------------------------------------------------------
__device__ __forceinline__ uint32_t smem_to_u32(const void* p) {
    uint32_t a;
    asm("{ .reg .u64 t; cvta.to.shared.u64 t, %1; cvt.u32.u64 %0, t; }"
        : "=r"(a) : "l"(p));
    return a;
}

__device__ __forceinline__ void cp_async16(uint32_t sdst, const void* gsrc, bool ok) {
    int sz = ok ? 16 : 0;
    asm volatile("cp.async.cg.shared.global [%0], [%1], 16, %2;\n"
                 :: "r"(sdst), "l"(gsrc), "r"(sz));
}
#define CP_COMMIT() asm volatile("cp.async.commit_group;\n" ::: "memory")
#define CP_WAIT(n)  asm volatile("cp.async.wait_group %0;\n" :: "n"(n) : "memory")

__device__ __forceinline__ void ldm_x4(uint32_t& r0, uint32_t& r1, uint32_t& r2,
                                       uint32_t& r3, uint32_t addr) {
    asm volatile("ldmatrix.sync.aligned.m8n8.x4.shared.b16 {%0,%1,%2,%3}, [%4];"
                 : "=r"(r0), "=r"(r1), "=r"(r2), "=r"(r3) : "r"(addr));
}

__device__ __forceinline__ void mma_bf16(float* c, const uint32_t* a, const uint32_t* b) {
    asm volatile(
        "mma.sync.aligned.m16n8k16.row.col.f32.bf16.bf16.f32 "
        "{%0,%1,%2,%3}, {%4,%5,%6,%7}, {%8,%9}, {%0,%1,%2,%3};"
        : "+f"(c[0]), "+f"(c[1]), "+f"(c[2]), "+f"(c[3])
        : "r"(a[0]), "r"(a[1]), "r"(a[2]), "r"(a[3]), "r"(b[0]), "r"(b[1]));
}

__device__ __forceinline__ uint32_t pack_bf16x2(float a, float b) {
    // returns (lo=a, hi=b) packed
    unsigned short ua = __bfloat16_as_ushort(__float2bfloat16(a));
    unsigned short ub = __bfloat16_as_ushort(__float2bfloat16(b));
    return (uint32_t)ua | ((uint32_t)ub << 16);
}

// ---------------------------------------------------------------------------
// CSR build
// ---------------------------------------------------------------------------
__global__ void zero_counts_kernel() {
    int i = blockIdx.x * blockDim.x + threadIdx.x;
    if (i < NNODES) { g_count[i] = 0; g_pos[i] = 0; }
}
__global__ void count_kernel(const int* __restrict__ dst) {
    int e = blockIdx.x * blockDim.x + threadIdx.x;
    if (e < NEDGES) atomicAdd(&g_count[dst[e]], 1);
}
__global__ void scan_kernel() {
    __shared__ int part[1024];
    const int tid = threadIdx.x;
    const int CH = (NNODES + 1023) / 1024;
    const int base = tid * CH;
    int s = 0;
    for (int i = 0; i < CH; ++i) {
        int idx = base + i;
        if (idx < NNODES) s += g_count[idx];
    }
    part[tid] = s;
    __syncthreads();
    for (int off = 1; off < 1024; off <<= 1) {
        int v = (tid >= off) ? part[tid - off] : 0;
        __syncthreads();
        part[tid] += v;
        __syncthreads();
    }
    int run = part[tid] - s;
    for (int i = 0; i < CH; ++i) {
        int idx = base + i;
        if (idx < NNODES) { g_offs[idx] = run; run += g_count[idx]; }
    }
    if (tid == 1023) g_offs[NNODES] = part[1023];
}
__global__ void fill_kernel(const int* __restrict__ src, const int* __restrict__ dst) {
    int e = blockIdx.x * blockDim.x + threadIdx.x;
    if (e < NEDGES) {
        int d = dst[e];
        int p = atomicAdd(&g_pos[d], 1);
        g_eidx[g_offs[d] + p] = src[e];
    }
}

// ---------------------------------------------------------------------------
// Conversion: fp32 -> (bf16 hi, bf16 lo), zero-padded; 4 elems/thread
// ---------------------------------------------------------------------------
__global__ void split_pad_kernel(const float* __restrict__ src,
                                 __nv_bfloat16* __restrict__ hi,
                                 __nv_bfloat16* __restrict__ lo,
                                 int M, int K, int Kpad) {
    size_t idx4 = (size_t)blockIdx.x * blockDim.x + threadIdx.x;
    size_t total4 = (size_t)M * (Kpad >> 2);
    if (idx4 >= total4) return;
    int gpr = Kpad >> 2;
    int r = (int)(idx4 / gpr);
    int c = (int)(idx4 % gpr) << 2;
    float v[4];
#pragma unroll
    for (int j = 0; j < 4; ++j) {
        int cj = c + j;
        v[j] = (cj < K) ? src[(size_t)r * K + cj] : 0.f;
    }
    uint32_t h01 = pack_bf16x2(v[0], v[1]);
    uint32_t h23 = pack_bf16x2(v[2], v[3]);
    float rlo[4];
#pragma unroll
    for (int j = 0; j < 4; ++j) {
        __nv_bfloat16 hj = __float2bfloat16(v[j]);
        rlo[j] = v[j] - __bfloat162float(hj);
    }
    uint32_t l01 = pack_bf16x2(rlo[0], rlo[1]);
    uint32_t l23 = pack_bf16x2(rlo[2], rlo[3]);
    size_t o = (size_t)r * Kpad + c;
    *reinterpret_cast<uint2*>(hi + o) = make_uint2(h01, h23);
    *reinterpret_cast<uint2*>(lo + o) = make_uint2(l01, l23);
}

// W [K,N] row-major -> Wt hi/lo [Npad][Kpad] (K-major rows), zero-padded
__global__ void transpose_split_kernel(const float* __restrict__ W,
                                       __nv_bfloat16* __restrict__ thi,
                                       __nv_bfloat16* __restrict__ tlo,
                                       int K, int N, int Kpad, int Npad) {
    size_t idx = (size_t)blockIdx.x * blockDim.x + threadIdx.x;
    size_t total = (size_t)Npad * Kpad;
    if (idx >= total) return;
    int n = (int)(idx / Kpad);
    int k = (int)(idx % Kpad);
    float x = (n < N && k < K) ? W[(size_t)k * N + n] : 0.f;
    __nv_bfloat16 h = __float2bfloat16(x);
    float res = x - __bfloat162float(h);
    thi[idx] = h;
    tlo[idx] = __float2bfloat16(res);
}

// ---------------------------------------------------------------------------
// HMMA GEMM, 3-stage cp.async pipeline, BK=64:
//   C[M, Nreal] = Ahi@Bhi^T + Alo@Bhi^T + Ahi@Blo^T   (fp32 accum)
// CTA tile 128x128, 8 warps (4m x 2n), warp tile 32x64.
// SMEM rows padded to 72 halves (conflict-free ldmatrix).
// ---------------------------------------------------------------------------
#define BK 64
#define ROW_H 72                                // halves per smem row (64 + 8)
#define MAT_BYTES ((uint32_t)(128 * ROW_H * 2)) // 18432
#define A_LO_OFF  MAT_BYTES
#define B_HI_OFF  (2 * MAT_BYTES)
#define B_LO_OFF  (3 * MAT_BYTES)
#define STAGE_BYTES (4 * MAT_BYTES)             // 73728
#define NSTAGE 3
#define GEMM_SMEM (NSTAGE * STAGE_BYTES)        // 221184

__global__ __launch_bounds__(256, 1)
void hmma_gemm3_kernel(const __nv_bfloat16* __restrict__ a_hi,
                       const __nv_bfloat16* __restrict__ a_lo,
                       const __nv_bfloat16* __restrict__ b_hi,
                       const __nv_bfloat16* __restrict__ b_lo,
                       float* __restrict__ C,
                       int M, int Nreal, int Kpad) {
    extern __shared__ __nv_bfloat16 smem[];
    const uint32_t smem_u32 = smem_to_u32(smem);
    const int t = threadIdx.x;
    const int lane = t & 31;
    const int wid = t >> 5;
    const int wm = wid & 3;
    const int wn = wid >> 2;
    const int m0 = blockIdx.y * 128;
    const int n0 = blockIdx.x * 128;
    const int nchunk = Kpad / BK;

    float acc[2][8][4];
#pragma unroll
    for (int i = 0; i < 2; ++i)
#pragma unroll
        for (int j = 0; j < 8; ++j)
#pragma unroll
            for (int k = 0; k < 4; ++k) acc[i][j][k] = 0.f;

    auto load_stage = [&](int c) {
        const int slot = c % NSTAGE;
        const int k0 = c * BK;
        const uint32_t sbase = smem_u32 + slot * STAGE_BYTES;
#pragma unroll
        for (int i = 0; i < 4; ++i) {
            int idx = t + i * 256;          // 0..1023
            int row = idx >> 3;             // 0..127
            int ch = idx & 7;               // 16B chunk within 128B of data
            uint32_t off = (uint32_t)(row * ROW_H + ch * 8) * 2;
            int gm = m0 + row;
            bool ok = gm < M;
            int gmc = ok ? gm : 0;
            size_t goa = (size_t)gmc * Kpad + k0 + ch * 8;
            cp_async16(sbase + off, a_hi + goa, ok);
            cp_async16(sbase + off + A_LO_OFF, a_lo + goa, ok);
            size_t gob = (size_t)(n0 + row) * Kpad + k0 + ch * 8;
            cp_async16(sbase + off + B_HI_OFF, b_hi + gob, true);
            cp_async16(sbase + off + B_LO_OFF, b_lo + gob, true);
        }
        CP_COMMIT();
    };

    // prologue: two stages in flight
    load_stage(0);
    load_stage(1);

    for (int c = 0; c < nchunk; ++c) {
        if (c + 1 < nchunk) { CP_WAIT(1); } else { CP_WAIT(0); }
        __syncthreads();   // stage c ready for all; compute(c-1) finished for all
        if (c + 2 < nchunk) load_stage(c + 2);   // into slot (c-1)%3, now free

        const uint32_t sb = smem_u32 + (uint32_t)(c % NSTAGE) * STAGE_BYTES;
#pragma unroll
        for (int ks = 0; ks < 4; ++ks) {
            const int k0s = ks * 16;
            uint32_t afh[2][4], afl[2][4];
            {
                int ar = lane & 15;
                int ak = k0s + (lane >> 4) * 8;
#pragma unroll
                for (int mt = 0; mt < 2; ++mt) {
                    uint32_t addr = sb +
                        (uint32_t)((wm * 32 + mt * 16 + ar) * ROW_H + ak) * 2;
                    ldm_x4(afh[mt][0], afh[mt][1], afh[mt][2], afh[mt][3], addr);
                    ldm_x4(afl[mt][0], afl[mt][1], afl[mt][2], afl[mt][3],
                           addr + A_LO_OFF);
                }
            }
            uint32_t bfh[8][2], bfl[8][2];
            {
                int brr = (lane & 7) + (lane >> 4) * 8;
                int bk = k0s + ((lane >> 3) & 1) * 8;
#pragma unroll
                for (int ng = 0; ng < 4; ++ng) {
                    uint32_t addr = sb + B_HI_OFF +
                        (uint32_t)((wn * 64 + ng * 16 + brr) * ROW_H + bk) * 2;
                    uint32_t r0, r1, r2, r3;
                    ldm_x4(r0, r1, r2, r3, addr);
                    bfh[2 * ng][0] = r0; bfh[2 * ng][1] = r1;
                    bfh[2 * ng + 1][0] = r2; bfh[2 * ng + 1][1] = r3;
                    ldm_x4(r0, r1, r2, r3, addr + MAT_BYTES);
                    bfl[2 * ng][0] = r0; bfl[2 * ng][1] = r1;
                    bfl[2 * ng + 1][0] = r2; bfl[2 * ng + 1][1] = r3;
                }
            }
#pragma unroll
            for (int mt = 0; mt < 2; ++mt) {
#pragma unroll
                for (int nt = 0; nt < 8; ++nt) {
                    mma_bf16(acc[mt][nt], afh[mt], bfh[nt]);
                    mma_bf16(acc[mt][nt], afl[mt], bfh[nt]);
                    mma_bf16(acc[mt][nt], afh[mt], bfl[nt]);
                }
            }
        }
    }

    // epilogue: direct float2 stores
#pragma unroll
    for (int mt = 0; mt < 2; ++mt) {
        int gr0 = m0 + wm * 32 + mt * 16 + (lane >> 2);
#pragma unroll
        for (int nt = 0; nt < 8; ++nt) {
            int gc = n0 + wn * 64 + nt * 8 + (lane & 3) * 2;
            if (gc >= Nreal) continue;
            if (gr0 < M) {
                float2 v = make_float2(acc[mt][nt][0], acc[mt][nt][1]);
                *reinterpret_cast<float2*>(&C[(size_t)gr0 * Nreal + gc]) = v;
            }
            if (gr0 + 8 < M) {
                float2 v = make_float2(acc[mt][nt][2], acc[mt][nt][3]);
                *reinterpret_cast<float2*>(&C[(size_t)(gr0 + 8) * Nreal + gc]) = v;
            }
        }
    }
}

// ---------------------------------------------------------------------------
// Aggregation + bias + relu, float4-vectorized.
// Split variant additionally emits bf16 hi/lo for the next GEMM.
// One CTA (256 threads) per node; thread d4 owns columns [4*d4, 4*d4+4).
// ---------------------------------------------------------------------------
__global__ __launch_bounds__(256)
void agg_bias_relu_split_kernel(const float* __restrict__ t,
                                const float* __restrict__ bias,
                                __nv_bfloat16* __restrict__ xhi,
                                __nv_bfloat16* __restrict__ xlo) {
    __shared__ int nbr[512];
    const int node = blockIdx.x;
    const int beg = g_offs[node], end = g_offs[node + 1];
    const int deg = end - beg;
    const int* elist;
    if (deg <= 512) {
        for (int i = threadIdx.x; i < deg; i += blockDim.x) nbr[i] = g_eidx[beg + i];
        __syncthreads();
        elist = nbr;
    } else {
        elist = g_eidx + beg;
    }
    const int d4 = threadIdx.x;           // 0..255, K2PAD/4 = 256 groups
    const int c = d4 << 2;
    const bool real = c < D_H1;           // D_H1 = 1000, multiple of 4
    float4 acc = make_float4(0.f, 0.f, 0.f, 0.f);
    if (real) {
        acc.x = bias[c]; acc.y = bias[c + 1]; acc.z = bias[c + 2]; acc.w = bias[c + 3];
        int e = 0;
        for (; e + 1 < deg; e += 2) {
            const float4 v0 = *reinterpret_cast<const float4*>(
                t + (size_t)elist[e] * D_H1 + c);
            const float4 v1 = *reinterpret_cast<const float4*>(
                t + (size_t)elist[e + 1] * D_H1 + c);
            acc.x += v0.x + v1.x; acc.y += v0.y + v1.y;
            acc.z += v0.z + v1.z; acc.w += v0.w + v1.w;
        }
        if (e < deg) {
            const float4 v0 = *reinterpret_cast<const float4*>(
                t + (size_t)elist[e] * D_H1 + c);
            acc.x += v0.x; acc.y += v0.y; acc.z += v0.z; acc.w += v0.w;
        }
        acc.x = fmaxf(acc.x, 0.f); acc.y = fmaxf(acc.y, 0.f);
        acc.z = fmaxf(acc.z, 0.f); acc.w = fmaxf(acc.w, 0.f);
    }
    float v[4] = {acc.x, acc.y, acc.z, acc.w};
    float rlo[4];
#pragma unroll
    for (int j = 0; j < 4; ++j) {
        __nv_bfloat16 hj = __float2bfloat16(v[j]);
        rlo[j] = v[j] - __bfloat162float(hj);
    }
    size_t o = (size_t)node * K2PAD + c;
    *reinterpret_cast<uint2*>(xhi + o) =
        make_uint2(pack_bf16x2(v[0], v[1]), pack_bf16x2(v[2], v[3]));
    *reinterpret_cast<uint2*>(xlo + o) =
        make_uint2(pack_bf16x2(rlo[0], rlo[1]), pack_bf16x2(rlo[2], rlo[3]));
}

// Layer-2 aggregation: D = 500 -> 125 float4 groups; 128 threads per node.
__global__ __launch_bounds__(128)
void agg_bias_relu_kernel(const float* __restrict__ t,
                          const float* __restrict__ bias,
                          float* __restrict__ out) {
    __shared__ int nbr[512];
    const int node = blockIdx.x;
    const int beg = g_offs[node], end = g_offs[node + 1];
    const int deg = end - beg;
    const int* elist;
    if (deg <= 512) {
        for (int i = threadIdx.x; i < deg; i += blockDim.x) nbr[i] = g_eidx[beg + i];
        __syncthreads();
        elist = nbr;
    } else {
        elist = g_eidx + beg;
    }
    const int d4 = threadIdx.x;
    const int c = d4 << 2;
    if (c >= D_H2) return;     // D_H2 = 500, multiple of 4 -> 125 groups
    float4 acc;
    acc.x = bias[c]; acc.y = bias[c + 1]; acc.z = bias[c + 2]; acc.w = bias[c + 3];
    int e = 0;
    for (; e + 1 < deg; e += 2) {
        const float4 v0 = *reinterpret_cast<const float4*>(
            t + (size_t)elist[e] * D_H2 + c);
        const float4 v1 = *reinterpret_cast<const float4*>(
            t + (size_t)elist[e + 1] * D_H2 + c);
        acc.x += v0.x + v1.x; acc.y += v0.y + v1.y;
        acc.z += v0.z + v1.z; acc.w += v0.w + v1.w;
    }
    if (e < deg) {
        const float4 v0 = *reinterpret_cast<const float4*>(
            t + (size_t)elist[e] * D_H2 + c);
        acc.x += v0.x; acc.y += v0.y; acc.z += v0.z; acc.w += v0.w;
    }
    float4 r = make_float4(fmaxf(acc.x, 0.f), fmaxf(acc.y, 0.f),
                           fmaxf(acc.z, 0.f), fmaxf(acc.w, 0.f));
    *reinterpret_cast<float4*>(out + (size_t)node * D_H2 + c) = r;
}

// ---------------------------------------------------------------------------
// Output layer: out[i,:7] = relu(x2[i,:] @ W3 + b3), one warp per row
// ---------------------------------------------------------------------------
__global__ void out_layer_kernel(const float* __restrict__ x2,
                                 const float* __restrict__ W3,
                                 const float* __restrict__ b3,
                                 float* __restrict__ out) {
    __shared__ float Ws[D_H2 * D_OUT];
    for (int i = threadIdx.x; i < D_H2 * D_OUT; i += blockDim.x) Ws[i] = W3[i];
    __syncthreads();
    const int warp = (blockIdx.x * blockDim.x + threadIdx.x) >> 5;
    const int lane = threadIdx.x & 31;
    if (warp >= NNODES) return;
    float acc[D_OUT] = {0.f, 0.f, 0.f, 0.f, 0.f, 0.f, 0.f};
    const float* row = x2 + (size_t)warp * D_H2;
    for (int k = lane; k < D_H2; k += 32) {
        float v = row[k];
#pragma unroll
        for (int j = 0; j < D_OUT; ++j) acc[j] += v * Ws[k * D_OUT + j];
    }
#pragma unroll
    for (int j = 0; j < D_OUT; ++j) {
#pragma unroll
        for (int off = 16; off > 0; off >>= 1)
            acc[j] += __shfl_xor_sync(0xFFFFFFFFu, acc[j], off);
    }
    if (lane == 0) {
#pragma unroll
        for (int j = 0; j < D_OUT; ++j)
            out[(size_t)warp * D_OUT + j] = fmaxf(acc[j] + b3[j], 0.f);
    }
}

// ---------------------------------------------------------------------------
// Launch
// ---------------------------------------------------------------------------
extern "C" void kernel_launch(void* const* d_in, const int* in_sizes, int n_in,
                              void* d_out, int out_size) {
    const float* features = (const float*)d_in[0];
    const int*   src      = (const int*)  d_in[1];
    const int*   dst      = (const int*)  d_in[2];
    const float* W1       = (const float*)d_in[3];
    const float* b1       = (const float*)d_in[4];
    const float* W2       = (const float*)d_in[5];
    const float* b2       = (const float*)d_in[6];
    const float* W3       = (const float*)d_in[7];
    const float* b3       = (const float*)d_in[8];
    float* out = (float*)d_out;

    __nv_bfloat16 *fa_hi, *fa_lo, *w1t_hi, *w1t_lo, *x1_hi, *x1_lo, *w2t_hi, *w2t_lo;
    float *t1, *t2, *x2;
    cudaGetSymbolAddress((void**)&fa_hi, g_fa_hi);
    cudaGetSymbolAddress((void**)&fa_lo, g_fa_lo);
    cudaGetSymbolAddress((void**)&w1t_hi, g_w1t_hi);
    cudaGetSymbolAddress((void**)&w1t_lo, g_w1t_lo);
    cudaGetSymbolAddress((void**)&x1_hi, g_x1_hi);
    cudaGetSymbolAddress((void**)&x1_lo, g_x1_lo);
    cudaGetSymbolAddress((void**)&w2t_hi, g_w2t_hi);
    cudaGetSymbolAddress((void**)&w2t_lo, g_w2t_lo);
    cudaGetSymbolAddress((void**)&t1, g_t1);
    cudaGetSymbolAddress((void**)&t2, g_t2);
    cudaGetSymbolAddress((void**)&x2, g_x2);

    cudaFuncSetAttribute(hmma_gemm3_kernel,
                         cudaFuncAttributeMaxDynamicSharedMemorySize, GEMM_SMEM);

    // CSR build
    zero_counts_kernel<<<(NNODES + 255) / 256, 256>>>();
    count_kernel<<<(NEDGES + 255) / 256, 256>>>(dst);
    scan_kernel<<<1, 1024>>>();
    fill_kernel<<<(NEDGES + 255) / 256, 256>>>(src, dst);

    // Conversions
    {
        size_t tot4 = (size_t)NNODES * (K1PAD / 4);
        split_pad_kernel<<<(unsigned)((tot4 + 255) / 256), 256>>>(
            features, fa_hi, fa_lo, NNODES, D_IN, K1PAD);
        size_t wt = (size_t)N1PAD * K1PAD;
        transpose_split_kernel<<<(unsigned)((wt + 255) / 256), 256>>>(
            W1, w1t_hi, w1t_lo, D_IN, D_H1, K1PAD, N1PAD);
        size_t wt2 = (size_t)N2PAD * K2PAD;
        transpose_split_kernel<<<(unsigned)((wt2 + 255) / 256), 256>>>(
            W2, w2t_hi, w2t_lo, D_H1, D_H2, K2PAD, N2PAD);
    }

    // Layer 1
    {
        dim3 grid(N1PAD / 128, (NNODES + 127) / 128);
        hmma_gemm3_kernel<<<grid, 256, GEMM_SMEM>>>(fa_hi, fa_lo, w1t_hi, w1t_lo,
                                                    t1, NNODES, D_H1, K1PAD);
        agg_bias_relu_split_kernel<<<NNODES, 256>>>(t1, b1, x1_hi, x1_lo);
    }

    // Layer 2
    {
        dim3 grid(N2PAD / 128, (NNODES + 127) / 128);
        hmma_gemm3_kernel<<<grid, 256, GEMM_SMEM>>>(x1_hi, x1_lo, w2t_hi, w2t_lo,
                                                    t2, NNODES, D_H2, K2PAD);
        agg_bias_relu_kernel<<<NNODES, 128>>>(t2, b2, x2);
    }

    // Output layer
    {
        int blocks = (NNODES + 7) / 8;
        out_layer_kernel<<<blocks, 256>>>(x2, W3, b3, out);
    }
}

// round 5
// speedup vs baseline: 3.8229x; 1.2490x over previous
#include <cuda_runtime.h>
#include <cuda_fp16.h>
#include <cuda_bf16.h>
#include <cstdint>

// Problem constants
#define NNODES 20000
#define NEDGES 200000
#define D_IN   1433
#define D_H1   1000
#define D_H2   500
#define D_OUT  7

// Padded GEMM dims
#define K1PAD  1472   // >= 1433, mult of 64
#define K2PAD  1024   // >= 1000, mult of 64
#define N1PAD  1024   // >= 1000, mult of 128
#define N2PAD  512    // >= 500,  mult of 128

// ---------------------------------------------------------------------------
// Device scratch
// ---------------------------------------------------------------------------
__device__ __align__(256) __half g_fa_hi[(size_t)NNODES * K1PAD];
__device__ __align__(256) __half g_fa_lo[(size_t)NNODES * K1PAD];
__device__ __align__(256) __half g_w1t[(size_t)N1PAD * K1PAD];
__device__ __align__(256) __half g_x1_hi[(size_t)NNODES * K2PAD];
__device__ __align__(256) __half g_x1_lo[(size_t)NNODES * K2PAD];
__device__ __align__(256) __half g_w2t[(size_t)N2PAD * K2PAD];
__device__ __align__(256) float g_t1[(size_t)NNODES * D_H1];
__device__ __align__(256) float g_t2[(size_t)NNODES * D_H2];
__device__ __align__(256) float g_x2[(size_t)NNODES * D_H2];
__device__ int g_count[NNODES];
__device__ int g_pos[NNODES];
__device__ int g_offs[NNODES + 1];
__device__ int g_eidx[NEDGES];

// ---------------------------------------------------------------------------
// PTX helpers (portable ISA: ldmatrix / mma.sync / cp.async)
// ---------------------------------------------------------------------------
__device__ __forceinline__ uint32_t smem_to_u32(const void* p) {
    uint32_t a;
    asm("{ .reg .u64 t; cvta.to.shared.u64 t, %1; cvt.u32.u64 %0, t; }"
        : "=r"(a) : "l"(p));
    return a;
}

__device__ __forceinline__ void cp_async16(uint32_t sdst, const void* gsrc, bool ok) {
    int sz = ok ? 16 : 0;
    asm volatile("cp.async.cg.shared.global [%0], [%1], 16, %2;\n"
                 :: "r"(sdst), "l"(gsrc), "r"(sz));
}
#define CP_COMMIT() asm volatile("cp.async.commit_group;\n" ::: "memory")
#define CP_WAIT(n)  asm volatile("cp.async.wait_group %0;\n" :: "n"(n) : "memory")

__device__ __forceinline__ void ldm_x4(uint32_t& r0, uint32_t& r1, uint32_t& r2,
                                       uint32_t& r3, uint32_t addr) {
    asm volatile("ldmatrix.sync.aligned.m8n8.x4.shared.b16 {%0,%1,%2,%3}, [%4];"
                 : "=r"(r0), "=r"(r1), "=r"(r2), "=r"(r3) : "r"(addr));
}

__device__ __forceinline__ void mma_f16(float* c, const uint32_t* a, const uint32_t* b) {
    asm volatile(
        "mma.sync.aligned.m16n8k16.row.col.f32.f16.f16.f32 "
        "{%0,%1,%2,%3}, {%4,%5,%6,%7}, {%8,%9}, {%0,%1,%2,%3};"
        : "+f"(c[0]), "+f"(c[1]), "+f"(c[2]), "+f"(c[3])
        : "r"(a[0]), "r"(a[1]), "r"(a[2]), "r"(a[3]), "r"(b[0]), "r"(b[1]));
}

__device__ __forceinline__ uint32_t pack_f16x2(float a, float b) {
    __half2 h = __floats2half2_rn(a, b);
    return *reinterpret_cast<uint32_t*>(&h);
}

// ---------------------------------------------------------------------------
// CSR build
// ---------------------------------------------------------------------------
__global__ void zero_counts_kernel() {
    int i = blockIdx.x * blockDim.x + threadIdx.x;
    if (i < NNODES) { g_count[i] = 0; g_pos[i] = 0; }
}
__global__ void count_kernel(const int* __restrict__ dst) {
    int e = blockIdx.x * blockDim.x + threadIdx.x;
    if (e < NEDGES) atomicAdd(&g_count[dst[e]], 1);
}
__global__ void scan_kernel() {
    __shared__ int part[1024];
    const int tid = threadIdx.x;
    const int CH = (NNODES + 1023) / 1024;
    const int base = tid * CH;
    int s = 0;
    for (int i = 0; i < CH; ++i) {
        int idx = base + i;
        if (idx < NNODES) s += g_count[idx];
    }
    part[tid] = s;
    __syncthreads();
    for (int off = 1; off < 1024; off <<= 1) {
        int v = (tid >= off) ? part[tid - off] : 0;
        __syncthreads();
        part[tid] += v;
        __syncthreads();
    }
    int run = part[tid] - s;
    for (int i = 0; i < CH; ++i) {
        int idx = base + i;
        if (idx < NNODES) { g_offs[idx] = run; run += g_count[idx]; }
    }
    if (tid == 1023) g_offs[NNODES] = part[1023];
}
__global__ void fill_kernel(const int* __restrict__ src, const int* __restrict__ dst) {
    int e = blockIdx.x * blockDim.x + threadIdx.x;
    if (e < NEDGES) {
        int d = dst[e];
        int p = atomicAdd(&g_pos[d], 1);
        g_eidx[g_offs[d] + p] = src[e];
    }
}

// ---------------------------------------------------------------------------
// Conversion: fp32 -> (fp16 hi, fp16 lo), zero-padded; 4 elems/thread
// ---------------------------------------------------------------------------
__global__ void split_pad_kernel(const float* __restrict__ src,
                                 __half* __restrict__ hi,
                                 __half* __restrict__ lo,
                                 int M, int K, int Kpad) {
    size_t idx4 = (size_t)blockIdx.x * blockDim.x + threadIdx.x;
    size_t total4 = (size_t)M * (Kpad >> 2);
    if (idx4 >= total4) return;
    int gpr = Kpad >> 2;
    int r = (int)(idx4 / gpr);
    int c = (int)(idx4 % gpr) << 2;
    float v[4], rlo[4];
#pragma unroll
    for (int j = 0; j < 4; ++j) {
        int cj = c + j;
        v[j] = (cj < K) ? src[(size_t)r * K + cj] : 0.f;
        __half hj = __float2half(v[j]);
        rlo[j] = v[j] - __half2float(hj);
    }
    size_t o = (size_t)r * Kpad + c;
    *reinterpret_cast<uint2*>(hi + o) =
        make_uint2(pack_f16x2(v[0], v[1]), pack_f16x2(v[2], v[3]));
    *reinterpret_cast<uint2*>(lo + o) =
        make_uint2(pack_f16x2(rlo[0], rlo[1]), pack_f16x2(rlo[2], rlo[3]));
}

// W [K,N] row-major -> Wt fp16 [Npad][Kpad] (K-major rows), zero-padded
__global__ void transpose_f16_kernel(const float* __restrict__ W,
                                     __half* __restrict__ t,
                                     int K, int N, int Kpad, int Npad) {
    size_t idx = (size_t)blockIdx.x * blockDim.x + threadIdx.x;
    size_t total = (size_t)Npad * Kpad;
    if (idx >= total) return;
    int n = (int)(idx / Kpad);
    int k = (int)(idx % Kpad);
    float x = (n < N && k < K) ? W[(size_t)k * N + n] : 0.f;
    t[idx] = __float2half(x);
}

// ---------------------------------------------------------------------------
// HMMA GEMM, 4-stage cp.async pipeline, BK=64, fp16 2-pass split:
//   C[M, Nreal] = Ahi@B^T + Alo@B^T   (fp32 accum; B pre-quantized fp16)
// CTA tile 128x128, 8 warps (4m x 2n), warp tile 32x64.
// SMEM rows padded to 72 halves (conflict-free ldmatrix).
// ---------------------------------------------------------------------------
#define BK 64
#define ROW_H 72                                // halves per smem row (64 + 8)
#define MAT_BYTES ((uint32_t)(128 * ROW_H * 2)) // 18432
#define A_LO_OFF  MAT_BYTES
#define B_OFF     (2 * MAT_BYTES)
#define STAGE_BYTES (3 * MAT_BYTES)             // 55296
#define NSTAGE 4
#define GEMM_SMEM (NSTAGE * STAGE_BYTES)        // 221184

__global__ __launch_bounds__(256, 1)
void hmma_gemm2_kernel(const __half* __restrict__ a_hi,
                       const __half* __restrict__ a_lo,
                       const __half* __restrict__ b,
                       float* __restrict__ C,
                       int M, int Nreal, int Kpad) {
    extern __shared__ __half smem[];
    const uint32_t smem_u32 = smem_to_u32(smem);
    const int t = threadIdx.x;
    const int lane = t & 31;
    const int wid = t >> 5;
    const int wm = wid & 3;
    const int wn = wid >> 2;
    const int m0 = blockIdx.y * 128;
    const int n0 = blockIdx.x * 128;
    const int nchunk = Kpad / BK;

    float acc[2][8][4];
#pragma unroll
    for (int i = 0; i < 2; ++i)
#pragma unroll
        for (int j = 0; j < 8; ++j)
#pragma unroll
            for (int k = 0; k < 4; ++k) acc[i][j][k] = 0.f;

    auto load_stage = [&](int c) {
        const int slot = c % NSTAGE;
        const int k0 = c * BK;
        const uint32_t sbase = smem_u32 + slot * STAGE_BYTES;
#pragma unroll
        for (int i = 0; i < 4; ++i) {
            int idx = t + i * 256;          // 0..1023
            int row = idx >> 3;             // 0..127
            int ch = idx & 7;               // 16B chunk within 128B of data
            uint32_t off = (uint32_t)(row * ROW_H + ch * 8) * 2;
            int gm = m0 + row;
            bool ok = gm < M;
            int gmc = ok ? gm : 0;
            size_t goa = (size_t)gmc * Kpad + k0 + ch * 8;
            cp_async16(sbase + off, a_hi + goa, ok);
            cp_async16(sbase + off + A_LO_OFF, a_lo + goa, ok);
            size_t gob = (size_t)(n0 + row) * Kpad + k0 + ch * 8;
            cp_async16(sbase + off + B_OFF, b + gob, true);
        }
        CP_COMMIT();
    };

    // prologue: three stages in flight
    load_stage(0);
    if (nchunk > 1) load_stage(1);
    if (nchunk > 2) load_stage(2);

    for (int c = 0; c < nchunk; ++c) {
        if (c + 2 < nchunk)      { CP_WAIT(2); }
        else if (c + 1 < nchunk) { CP_WAIT(1); }
        else                     { CP_WAIT(0); }
        __syncthreads();   // stage c ready; all warps done with compute(c-1)
        if (c + 3 < nchunk) load_stage(c + 3);   // slot (c-1)%4, now free

        const uint32_t sb = smem_u32 + (uint32_t)(c % NSTAGE) * STAGE_BYTES;
#pragma unroll
        for (int ks = 0; ks < 4; ++ks) {
            const int k0s = ks * 16;
            uint32_t afh[2][4], afl[2][4];
            {
                int ar = lane & 15;
                int ak = k0s + (lane >> 4) * 8;
#pragma unroll
                for (int mt = 0; mt < 2; ++mt) {
                    uint32_t addr = sb +
                        (uint32_t)((wm * 32 + mt * 16 + ar) * ROW_H + ak) * 2;
                    ldm_x4(afh[mt][0], afh[mt][1], afh[mt][2], afh[mt][3], addr);
                    ldm_x4(afl[mt][0], afl[mt][1], afl[mt][2], afl[mt][3],
                           addr + A_LO_OFF);
                }
            }
            uint32_t bf[8][2];
            {
                int brr = (lane & 7) + (lane >> 4) * 8;
                int bk = k0s + ((lane >> 3) & 1) * 8;
#pragma unroll
                for (int ng = 0; ng < 4; ++ng) {
                    uint32_t addr = sb + B_OFF +
                        (uint32_t)((wn * 64 + ng * 16 + brr) * ROW_H + bk) * 2;
                    uint32_t r0, r1, r2, r3;
                    ldm_x4(r0, r1, r2, r3, addr);
                    bf[2 * ng][0] = r0; bf[2 * ng][1] = r1;
                    bf[2 * ng + 1][0] = r2; bf[2 * ng + 1][1] = r3;
                }
            }
#pragma unroll
            for (int mt = 0; mt < 2; ++mt) {
#pragma unroll
                for (int nt = 0; nt < 8; ++nt) {
                    mma_f16(acc[mt][nt], afh[mt], bf[nt]);
                    mma_f16(acc[mt][nt], afl[mt], bf[nt]);
                }
            }
        }
    }

    // epilogue: direct float2 stores
#pragma unroll
    for (int mt = 0; mt < 2; ++mt) {
        int gr0 = m0 + wm * 32 + mt * 16 + (lane >> 2);
#pragma unroll
        for (int nt = 0; nt < 8; ++nt) {
            int gc = n0 + wn * 64 + nt * 8 + (lane & 3) * 2;
            if (gc >= Nreal) continue;
            if (gr0 < M) {
                float2 v = make_float2(acc[mt][nt][0], acc[mt][nt][1]);
                *reinterpret_cast<float2*>(&C[(size_t)gr0 * Nreal + gc]) = v;
            }
            if (gr0 + 8 < M) {
                float2 v = make_float2(acc[mt][nt][2], acc[mt][nt][3]);
                *reinterpret_cast<float2*>(&C[(size_t)(gr0 + 8) * Nreal + gc]) = v;
            }
        }
    }
}

// ---------------------------------------------------------------------------
// Aggregation + bias + relu, float4-vectorized.
// Split variant emits fp16 hi/lo for the next GEMM.
// ---------------------------------------------------------------------------
__global__ __launch_bounds__(256)
void agg_bias_relu_split_kernel(const float* __restrict__ t,
                                const float* __restrict__ bias,
                                __half* __restrict__ xhi,
                                __half* __restrict__ xlo) {
    __shared__ int nbr[512];
    const int node = blockIdx.x;
    const int beg = g_offs[node], end = g_offs[node + 1];
    const int deg = end - beg;
    const int* elist;
    if (deg <= 512) {
        for (int i = threadIdx.x; i < deg; i += blockDim.x) nbr[i] = g_eidx[beg + i];
        __syncthreads();
        elist = nbr;
    } else {
        elist = g_eidx + beg;
    }
    const int d4 = threadIdx.x;           // 0..255, K2PAD/4 = 256 groups
    const int c = d4 << 2;
    const bool real = c < D_H1;           // D_H1 = 1000, multiple of 4
    float4 acc = make_float4(0.f, 0.f, 0.f, 0.f);
    if (real) {
        acc.x = bias[c]; acc.y = bias[c + 1]; acc.z = bias[c + 2]; acc.w = bias[c + 3];
        int e = 0;
        for (; e + 1 < deg; e += 2) {
            const float4 v0 = *reinterpret_cast<const float4*>(
                t + (size_t)elist[e] * D_H1 + c);
            const float4 v1 = *reinterpret_cast<const float4*>(
                t + (size_t)elist[e + 1] * D_H1 + c);
            acc.x += v0.x + v1.x; acc.y += v0.y + v1.y;
            acc.z += v0.z + v1.z; acc.w += v0.w + v1.w;
        }
        if (e < deg) {
            const float4 v0 = *reinterpret_cast<const float4*>(
                t + (size_t)elist[e] * D_H1 + c);
            acc.x += v0.x; acc.y += v0.y; acc.z += v0.z; acc.w += v0.w;
        }
        acc.x = fmaxf(acc.x, 0.f); acc.y = fmaxf(acc.y, 0.f);
        acc.z = fmaxf(acc.z, 0.f); acc.w = fmaxf(acc.w, 0.f);
    }
    float v[4] = {acc.x, acc.y, acc.z, acc.w};
    float rlo[4];
#pragma unroll
    for (int j = 0; j < 4; ++j) {
        __half hj = __float2half(v[j]);
        rlo[j] = v[j] - __half2float(hj);
    }
    size_t o = (size_t)node * K2PAD + c;
    *reinterpret_cast<uint2*>(xhi + o) =
        make_uint2(pack_f16x2(v[0], v[1]), pack_f16x2(v[2], v[3]));
    *reinterpret_cast<uint2*>(xlo + o) =
        make_uint2(pack_f16x2(rlo[0], rlo[1]), pack_f16x2(rlo[2], rlo[3]));
}

// Layer-2 aggregation: D = 500 -> 125 float4 groups; 128 threads per node.
__global__ __launch_bounds__(128)
void agg_bias_relu_kernel(const float* __restrict__ t,
                          const float* __restrict__ bias,
                          float* __restrict__ out) {
    __shared__ int nbr[512];
    const int node = blockIdx.x;
    const int beg = g_offs[node], end = g_offs[node + 1];
    const int deg = end - beg;
    const int* elist;
    if (deg <= 512) {
        for (int i = threadIdx.x; i < deg; i += blockDim.x) nbr[i] = g_eidx[beg + i];
        __syncthreads();
        elist = nbr;
    } else {
        elist = g_eidx + beg;
    }
    const int d4 = threadIdx.x;
    const int c = d4 << 2;
    if (c >= D_H2) return;     // D_H2 = 500, multiple of 4 -> 125 groups
    float4 acc;
    acc.x = bias[c]; acc.y = bias[c + 1]; acc.z = bias[c + 2]; acc.w = bias[c + 3];
    int e = 0;
    for (; e + 1 < deg; e += 2) {
        const float4 v0 = *reinterpret_cast<const float4*>(
            t + (size_t)elist[e] * D_H2 + c);
        const float4 v1 = *reinterpret_cast<const float4*>(
            t + (size_t)elist[e + 1] * D_H2 + c);
        acc.x += v0.x + v1.x; acc.y += v0.y + v1.y;
        acc.z += v0.z + v1.z; acc.w += v0.w + v1.w;
    }
    if (e < deg) {
        const float4 v0 = *reinterpret_cast<const float4*>(
            t + (size_t)elist[e] * D_H2 + c);
        acc.x += v0.x; acc.y += v0.y; acc.z += v0.z; acc.w += v0.w;
    }
    float4 r = make_float4(fmaxf(acc.x, 0.f), fmaxf(acc.y, 0.f),
                           fmaxf(acc.z, 0.f), fmaxf(acc.w, 0.f));
    *reinterpret_cast<float4*>(out + (size_t)node * D_H2 + c) = r;
}

// ---------------------------------------------------------------------------
// Output layer: out[i,:7] = relu(x2[i,:] @ W3 + b3), one warp per row
// ---------------------------------------------------------------------------
__global__ void out_layer_kernel(const float* __restrict__ x2,
                                 const float* __restrict__ W3,
                                 const float* __restrict__ b3,
                                 float* __restrict__ out) {
    __shared__ float Ws[D_H2 * D_OUT];
    for (int i = threadIdx.x; i < D_H2 * D_OUT; i += blockDim.x) Ws[i] = W3[i];
    __syncthreads();
    const int warp = (blockIdx.x * blockDim.x + threadIdx.x) >> 5;
    const int lane = threadIdx.x & 31;
    if (warp >= NNODES) return;
    float acc[D_OUT] = {0.f, 0.f, 0.f, 0.f, 0.f, 0.f, 0.f};
    const float* row = x2 + (size_t)warp * D_H2;
    for (int k = lane; k < D_H2; k += 32) {
        float v = row[k];
#pragma unroll
        for (int j = 0; j < D_OUT; ++j) acc[j] += v * Ws[k * D_OUT + j];
    }
#pragma unroll
    for (int j = 0; j < D_OUT; ++j) {
#pragma unroll
        for (int off = 16; off > 0; off >>= 1)
            acc[j] += __shfl_xor_sync(0xFFFFFFFFu, acc[j], off);
    }
    if (lane == 0) {
#pragma unroll
        for (int j = 0; j < D_OUT; ++j)
            out[(size_t)warp * D_OUT + j] = fmaxf(acc[j] + b3[j], 0.f);
    }
}

// ---------------------------------------------------------------------------
// Launch
// ---------------------------------------------------------------------------
extern "C" void kernel_launch(void* const* d_in, const int* in_sizes, int n_in,
                              void* d_out, int out_size) {
    const float* features = (const float*)d_in[0];
    const int*   src      = (const int*)  d_in[1];
    const int*   dst      = (const int*)  d_in[2];
    const float* W1       = (const float*)d_in[3];
    const float* b1       = (const float*)d_in[4];
    const float* W2       = (const float*)d_in[5];
    const float* b2       = (const float*)d_in[6];
    const float* W3       = (const float*)d_in[7];
    const float* b3       = (const float*)d_in[8];
    float* out = (float*)d_out;

    __half *fa_hi, *fa_lo, *w1t, *x1_hi, *x1_lo, *w2t;
    float *t1, *t2, *x2;
    cudaGetSymbolAddress((void**)&fa_hi, g_fa_hi);
    cudaGetSymbolAddress((void**)&fa_lo, g_fa_lo);
    cudaGetSymbolAddress((void**)&w1t, g_w1t);
    cudaGetSymbolAddress((void**)&x1_hi, g_x1_hi);
    cudaGetSymbolAddress((void**)&x1_lo, g_x1_lo);
    cudaGetSymbolAddress((void**)&w2t, g_w2t);
    cudaGetSymbolAddress((void**)&t1, g_t1);
    cudaGetSymbolAddress((void**)&t2, g_t2);
    cudaGetSymbolAddress((void**)&x2, g_x2);

    cudaFuncSetAttribute(hmma_gemm2_kernel,
                         cudaFuncAttributeMaxDynamicSharedMemorySize, GEMM_SMEM);

    // CSR build
    zero_counts_kernel<<<(NNODES + 255) / 256, 256>>>();
    count_kernel<<<(NEDGES + 255) / 256, 256>>>(dst);
    scan_kernel<<<1, 1024>>>();
    fill_kernel<<<(NEDGES + 255) / 256, 256>>>(src, dst);

    // Conversions
    {
        size_t tot4 = (size_t)NNODES * (K1PAD / 4);
        split_pad_kernel<<<(unsigned)((tot4 + 255) / 256), 256>>>(
            features, fa_hi, fa_lo, NNODES, D_IN, K1PAD);
        size_t wt = (size_t)N1PAD * K1PAD;
        transpose_f16_kernel<<<(unsigned)((wt + 255) / 256), 256>>>(
            W1, w1t, D_IN, D_H1, K1PAD, N1PAD);
        size_t wt2 = (size_t)N2PAD * K2PAD;
        transpose_f16_kernel<<<(unsigned)((wt2 + 255) / 256), 256>>>(
            W2, w2t, D_H1, D_H2, K2PAD, N2PAD);
    }

    // Layer 1
    {
        dim3 grid(N1PAD / 128, (NNODES + 127) / 128);
        hmma_gemm2_kernel<<<grid, 256, GEMM_SMEM>>>(fa_hi, fa_lo, w1t,
                                                    t1, NNODES, D_H1, K1PAD);
        agg_bias_relu_split_kernel<<<NNODES, 256>>>(t1, b1, x1_hi, x1_lo);
    }

    // Layer 2
    {
        dim3 grid(N2PAD / 128, (NNODES + 127) / 128);
        hmma_gemm2_kernel<<<grid, 256, GEMM_SMEM>>>(x1_hi, x1_lo, w2t,
                                                    t2, NNODES, D_H2, K2PAD);
        agg_bias_relu_kernel<<<NNODES, 128>>>(t2, b2, x2);
    }

    // Output layer
    {
        int blocks = (NNODES + 7) / 8;
        out_layer_kernel<<<blocks, 256>>>(x2, W3, b3, out);
    }
}

// round 6
// speedup vs baseline: 5.4335x; 1.4213x over previous
#include <cuda_runtime.h>
#include <cuda_fp16.h>
#include <cstdint>

// Problem constants
#define NNODES 20000
#define NEDGES 200000
#define D_IN   1433
#define D_H1   1000
#define D_H2   500
#define D_OUT  7

// Padded GEMM dims
#define K1PAD  1472   // >= 1433, mult of 64
#define K2PAD  1024   // >= 1000, mult of 64
#define N1PAD  1024   // >= 1000, mult of 128
#define N2PAD  512    // >= 500,  mult of 128

// ---------------------------------------------------------------------------
// Device scratch
// ---------------------------------------------------------------------------
__device__ __align__(256) __half g_fa[(size_t)NNODES * K1PAD];    // fp16 features, padded
__device__ __align__(256) __half g_w1t[(size_t)N1PAD * K1PAD];    // W1^T fp16
__device__ __align__(256) __half g_x1[(size_t)NNODES * K2PAD];    // relu(agg(t1)+b1) fp16, padded
__device__ __align__(256) __half g_w2t[(size_t)N2PAD * K2PAD];    // W2^T fp16
__device__ __align__(256) __half g_t1[(size_t)NNODES * D_H1];     // features @ W1, fp16
__device__ __align__(256) __half g_t2[(size_t)NNODES * D_H2];     // x1 @ W2, fp16
__device__ __align__(256) float  g_x2[(size_t)NNODES * D_H2];     // relu(agg(t2)+b2) fp32
__device__ int g_count[NNODES];
__device__ int g_pos[NNODES];
__device__ int g_offs[NNODES + 1];
__device__ int g_eidx[NEDGES];

// ---------------------------------------------------------------------------
// PTX helpers (portable ISA: ldmatrix / mma.sync / cp.async)
// ---------------------------------------------------------------------------
__device__ __forceinline__ uint32_t smem_to_u32(const void* p) {
    uint32_t a;
    asm("{ .reg .u64 t; cvta.to.shared.u64 t, %1; cvt.u32.u64 %0, t; }"
        : "=r"(a) : "l"(p));
    return a;
}

__device__ __forceinline__ void cp_async16(uint32_t sdst, const void* gsrc, bool ok) {
    int sz = ok ? 16 : 0;
    asm volatile("cp.async.cg.shared.global [%0], [%1], 16, %2;\n"
                 :: "r"(sdst), "l"(gsrc), "r"(sz));
}
#define CP_COMMIT() asm volatile("cp.async.commit_group;\n" ::: "memory")
#define CP_WAIT(n)  asm volatile("cp.async.wait_group %0;\n" :: "n"(n) : "memory")

__device__ __forceinline__ void ldm_x4(uint32_t& r0, uint32_t& r1, uint32_t& r2,
                                       uint32_t& r3, uint32_t addr) {
    asm volatile("ldmatrix.sync.aligned.m8n8.x4.shared.b16 {%0,%1,%2,%3}, [%4];"
                 : "=r"(r0), "=r"(r1), "=r"(r2), "=r"(r3) : "r"(addr));
}

__device__ __forceinline__ void mma_f16(float* c, const uint32_t* a, const uint32_t* b) {
    asm volatile(
        "mma.sync.aligned.m16n8k16.row.col.f32.f16.f16.f32 "
        "{%0,%1,%2,%3}, {%4,%5,%6,%7}, {%8,%9}, {%0,%1,%2,%3};"
        : "+f"(c[0]), "+f"(c[1]), "+f"(c[2]), "+f"(c[3])
        : "r"(a[0]), "r"(a[1]), "r"(a[2]), "r"(a[3]), "r"(b[0]), "r"(b[1]));
}

__device__ __forceinline__ uint32_t pack_f16x2(float a, float b) {
    __half2 h = __floats2half2_rn(a, b);
    return *reinterpret_cast<uint32_t*>(&h);
}

struct __align__(8) half4 { __half2 a, b; };

// ---------------------------------------------------------------------------
// CSR build
// ---------------------------------------------------------------------------
__global__ void zero_counts_kernel() {
    int i = blockIdx.x * blockDim.x + threadIdx.x;
    if (i < NNODES) { g_count[i] = 0; g_pos[i] = 0; }
}
__global__ void count_kernel(const int* __restrict__ dst) {
    int e = blockIdx.x * blockDim.x + threadIdx.x;
    if (e < NEDGES) atomicAdd(&g_count[dst[e]], 1);
}
__global__ void scan_kernel() {
    __shared__ int part[1024];
    const int tid = threadIdx.x;
    const int CH = (NNODES + 1023) / 1024;
    const int base = tid * CH;
    int s = 0;
    for (int i = 0; i < CH; ++i) {
        int idx = base + i;
        if (idx < NNODES) s += g_count[idx];
    }
    part[tid] = s;
    __syncthreads();
    for (int off = 1; off < 1024; off <<= 1) {
        int v = (tid >= off) ? part[tid - off] : 0;
        __syncthreads();
        part[tid] += v;
        __syncthreads();
    }
    int run = part[tid] - s;
    for (int i = 0; i < CH; ++i) {
        int idx = base + i;
        if (idx < NNODES) { g_offs[idx] = run; run += g_count[idx]; }
    }
    if (tid == 1023) g_offs[NNODES] = part[1023];
}
__global__ void fill_kernel(const int* __restrict__ src, const int* __restrict__ dst) {
    int e = blockIdx.x * blockDim.x + threadIdx.x;
    if (e < NEDGES) {
        int d = dst[e];
        int p = atomicAdd(&g_pos[d], 1);
        g_eidx[g_offs[d] + p] = src[e];
    }
}

// ---------------------------------------------------------------------------
// Conversion: fp32 -> fp16, zero-padded; 4 elems/thread
// ---------------------------------------------------------------------------
__global__ void quantize_pad_kernel(const float* __restrict__ src,
                                    __half* __restrict__ dstq,
                                    int M, int K, int Kpad) {
    size_t idx4 = (size_t)blockIdx.x * blockDim.x + threadIdx.x;
    size_t total4 = (size_t)M * (Kpad >> 2);
    if (idx4 >= total4) return;
    int gpr = Kpad >> 2;
    int r = (int)(idx4 / gpr);
    int c = (int)(idx4 % gpr) << 2;
    float v[4];
#pragma unroll
    for (int j = 0; j < 4; ++j) {
        int cj = c + j;
        v[j] = (cj < K) ? src[(size_t)r * K + cj] : 0.f;
    }
    size_t o = (size_t)r * Kpad + c;
    *reinterpret_cast<uint2*>(dstq + o) =
        make_uint2(pack_f16x2(v[0], v[1]), pack_f16x2(v[2], v[3]));
}

// W [K,N] row-major -> Wt fp16 [Npad][Kpad] (K-major rows), zero-padded
__global__ void transpose_f16_kernel(const float* __restrict__ W,
                                     __half* __restrict__ t,
                                     int K, int N, int Kpad, int Npad) {
    size_t idx = (size_t)blockIdx.x * blockDim.x + threadIdx.x;
    size_t total = (size_t)Npad * Kpad;
    if (idx >= total) return;
    int n = (int)(idx / Kpad);
    int k = (int)(idx % Kpad);
    float x = (n < N && k < K) ? W[(size_t)k * N + n] : 0.f;
    t[idx] = __float2half(x);
}

// ---------------------------------------------------------------------------
// HMMA GEMM, 5-stage cp.async pipeline, BK=64, single-pass fp16:
//   C[M, Nreal](fp16) = A@B^T   (fp32 accum; A, B fp16)
// CTA tile 128x128, 8 warps (4m x 2n), warp tile 32x64.
// SMEM rows padded to 72 halves (conflict-free ldmatrix).
// ---------------------------------------------------------------------------
#define BK 64
#define ROW_H 72                                // halves per smem row (64 + 8)
#define MAT_BYTES ((uint32_t)(128 * ROW_H * 2)) // 18432
#define B_OFF     MAT_BYTES
#define STAGE_BYTES (2 * MAT_BYTES)             // 36864
#define NSTAGE 5
#define GEMM_SMEM (NSTAGE * STAGE_BYTES)        // 184320

__global__ __launch_bounds__(256, 1)
void hmma_gemm_f16_kernel(const __half* __restrict__ a,
                          const __half* __restrict__ b,
                          __half* __restrict__ C,
                          int M, int Nreal, int Kpad) {
    extern __shared__ __half smem[];
    const uint32_t smem_u32 = smem_to_u32(smem);
    const int t = threadIdx.x;
    const int lane = t & 31;
    const int wid = t >> 5;
    const int wm = wid & 3;
    const int wn = wid >> 2;
    const int m0 = blockIdx.y * 128;
    const int n0 = blockIdx.x * 128;
    const int nchunk = Kpad / BK;

    float acc[2][8][4];
#pragma unroll
    for (int i = 0; i < 2; ++i)
#pragma unroll
        for (int j = 0; j < 8; ++j)
#pragma unroll
            for (int k = 0; k < 4; ++k) acc[i][j][k] = 0.f;

    auto load_stage = [&](int c) {
        const int slot = c % NSTAGE;
        const int k0 = c * BK;
        const uint32_t sbase = smem_u32 + slot * STAGE_BYTES;
#pragma unroll
        for (int i = 0; i < 4; ++i) {
            int idx = t + i * 256;          // 0..1023
            int row = idx >> 3;             // 0..127
            int ch = idx & 7;               // 16B chunk within 128B row
            uint32_t off = (uint32_t)(row * ROW_H + ch * 8) * 2;
            int gm = m0 + row;
            bool ok = gm < M;
            int gmc = ok ? gm : 0;
            size_t goa = (size_t)gmc * Kpad + k0 + ch * 8;
            cp_async16(sbase + off, a + goa, ok);
            size_t gob = (size_t)(n0 + row) * Kpad + k0 + ch * 8;
            cp_async16(sbase + off + B_OFF, b + gob, true);
        }
        CP_COMMIT();
    };

    // prologue: up to NSTAGE-1 stages in flight
#pragma unroll
    for (int p = 0; p < NSTAGE - 1; ++p)
        if (p < nchunk) load_stage(p);

    for (int c = 0; c < nchunk; ++c) {
        if (c + 3 < nchunk)      { CP_WAIT(3); }
        else if (c + 2 < nchunk) { CP_WAIT(2); }
        else if (c + 1 < nchunk) { CP_WAIT(1); }
        else                     { CP_WAIT(0); }
        __syncthreads();   // stage c ready; all warps done with compute(c-1)
        if (c + NSTAGE - 1 < nchunk) load_stage(c + NSTAGE - 1);

        const uint32_t sb = smem_u32 + (uint32_t)(c % NSTAGE) * STAGE_BYTES;
#pragma unroll
        for (int ks = 0; ks < 4; ++ks) {
            const int k0s = ks * 16;
            uint32_t af[2][4];
            {
                int ar = lane & 15;
                int ak = k0s + (lane >> 4) * 8;
#pragma unroll
                for (int mt = 0; mt < 2; ++mt) {
                    uint32_t addr = sb +
                        (uint32_t)((wm * 32 + mt * 16 + ar) * ROW_H + ak) * 2;
                    ldm_x4(af[mt][0], af[mt][1], af[mt][2], af[mt][3], addr);
                }
            }
            uint32_t bf[8][2];
            {
                int brr = (lane & 7) + (lane >> 4) * 8;
                int bk = k0s + ((lane >> 3) & 1) * 8;
#pragma unroll
                for (int ng = 0; ng < 4; ++ng) {
                    uint32_t addr = sb + B_OFF +
                        (uint32_t)((wn * 64 + ng * 16 + brr) * ROW_H + bk) * 2;
                    uint32_t r0, r1, r2, r3;
                    ldm_x4(r0, r1, r2, r3, addr);
                    bf[2 * ng][0] = r0; bf[2 * ng][1] = r1;
                    bf[2 * ng + 1][0] = r2; bf[2 * ng + 1][1] = r3;
                }
            }
#pragma unroll
            for (int mt = 0; mt < 2; ++mt) {
#pragma unroll
                for (int nt = 0; nt < 8; ++nt) {
                    mma_f16(acc[mt][nt], af[mt], bf[nt]);
                }
            }
        }
    }

    // epilogue: fp16 packed stores (pairs of columns)
#pragma unroll
    for (int mt = 0; mt < 2; ++mt) {
        int gr0 = m0 + wm * 32 + mt * 16 + (lane >> 2);
#pragma unroll
        for (int nt = 0; nt < 8; ++nt) {
            int gc = n0 + wn * 64 + nt * 8 + (lane & 3) * 2;
            if (gc >= Nreal) continue;   // Nreal even -> pair never straddles
            if (gr0 < M) {
                *reinterpret_cast<uint32_t*>(&C[(size_t)gr0 * Nreal + gc]) =
                    pack_f16x2(acc[mt][nt][0], acc[mt][nt][1]);
            }
            if (gr0 + 8 < M) {
                *reinterpret_cast<uint32_t*>(&C[(size_t)(gr0 + 8) * Nreal + gc]) =
                    pack_f16x2(acc[mt][nt][2], acc[mt][nt][3]);
            }
        }
    }
}

// ---------------------------------------------------------------------------
// Aggregation 1: x1[i,:] = relu(b1 + sum_j t1[j,:]) -> fp16, padded to K2PAD
// fp16 reads, fp32 accumulation. One CTA (256 threads) per node; 4 cols/thread.
// ---------------------------------------------------------------------------
__global__ __launch_bounds__(256)
void agg1_kernel(const __half* __restrict__ t,
                 const float* __restrict__ bias,
                 __half* __restrict__ x1) {
    __shared__ int nbr[512];
    const int node = blockIdx.x;
    const int beg = g_offs[node], end = g_offs[node + 1];
    const int deg = end - beg;
    const int* elist;
    if (deg <= 512) {
        for (int i = threadIdx.x; i < deg; i += blockDim.x) nbr[i] = g_eidx[beg + i];
        __syncthreads();
        elist = nbr;
    } else {
        elist = g_eidx + beg;
    }
    const int c = threadIdx.x << 2;       // 0..1020
    float a0 = 0.f, a1 = 0.f, a2 = 0.f, a3 = 0.f;
    if (c < D_H1) {
        a0 = bias[c]; a1 = bias[c + 1]; a2 = bias[c + 2]; a3 = bias[c + 3];
        for (int e = 0; e < deg; ++e) {
            const half4 v = *reinterpret_cast<const half4*>(
                t + (size_t)elist[e] * D_H1 + c);
            float2 p = __half22float2(v.a);
            float2 q = __half22float2(v.b);
            a0 += p.x; a1 += p.y; a2 += q.x; a3 += q.y;
        }
        a0 = fmaxf(a0, 0.f); a1 = fmaxf(a1, 0.f);
        a2 = fmaxf(a2, 0.f); a3 = fmaxf(a3, 0.f);
    }
    size_t o = (size_t)node * K2PAD + c;
    *reinterpret_cast<uint2*>(x1 + o) =
        make_uint2(pack_f16x2(a0, a1), pack_f16x2(a2, a3));
}

// Aggregation 2: x2[i,:] = relu(b2 + sum_j t2[j,:]) -> fp32. 128 thr/node.
__global__ __launch_bounds__(128)
void agg2_kernel(const __half* __restrict__ t,
                 const float* __restrict__ bias,
                 float* __restrict__ out) {
    __shared__ int nbr[512];
    const int node = blockIdx.x;
    const int beg = g_offs[node], end = g_offs[node + 1];
    const int deg = end - beg;
    const int* elist;
    if (deg <= 512) {
        for (int i = threadIdx.x; i < deg; i += blockDim.x) nbr[i] = g_eidx[beg + i];
        __syncthreads();
        elist = nbr;
    } else {
        elist = g_eidx + beg;
    }
    const int c = threadIdx.x << 2;
    if (c >= D_H2) return;     // D_H2 = 500 -> 125 groups
    float a0 = bias[c], a1 = bias[c + 1], a2 = bias[c + 2], a3 = bias[c + 3];
    for (int e = 0; e < deg; ++e) {
        const half4 v = *reinterpret_cast<const half4*>(
            t + (size_t)elist[e] * D_H2 + c);
        float2 p = __half22float2(v.a);
        float2 q = __half22float2(v.b);
        a0 += p.x; a1 += p.y; a2 += q.x; a3 += q.y;
    }
    float4 r = make_float4(fmaxf(a0, 0.f), fmaxf(a1, 0.f),
                           fmaxf(a2, 0.f), fmaxf(a3, 0.f));
    *reinterpret_cast<float4*>(out + (size_t)node * D_H2 + c) = r;
}

// ---------------------------------------------------------------------------
// Output layer: out[i,:7] = relu(x2[i,:] @ W3 + b3), one warp per row
// ---------------------------------------------------------------------------
__global__ void out_layer_kernel(const float* __restrict__ x2,
                                 const float* __restrict__ W3,
                                 const float* __restrict__ b3,
                                 float* __restrict__ out) {
    __shared__ float Ws[D_H2 * D_OUT];
    for (int i = threadIdx.x; i < D_H2 * D_OUT; i += blockDim.x) Ws[i] = W3[i];
    __syncthreads();
    const int warp = (blockIdx.x * blockDim.x + threadIdx.x) >> 5;
    const int lane = threadIdx.x & 31;
    if (warp >= NNODES) return;
    float acc[D_OUT] = {0.f, 0.f, 0.f, 0.f, 0.f, 0.f, 0.f};
    const float* row = x2 + (size_t)warp * D_H2;
    for (int k = lane; k < D_H2; k += 32) {
        float v = row[k];
#pragma unroll
        for (int j = 0; j < D_OUT; ++j) acc[j] += v * Ws[k * D_OUT + j];
    }
#pragma unroll
    for (int j = 0; j < D_OUT; ++j) {
#pragma unroll
        for (int off = 16; off > 0; off >>= 1)
            acc[j] += __shfl_xor_sync(0xFFFFFFFFu, acc[j], off);
    }
    if (lane == 0) {
#pragma unroll
        for (int j = 0; j < D_OUT; ++j)
            out[(size_t)warp * D_OUT + j] = fmaxf(acc[j] + b3[j], 0.f);
    }
}

// ---------------------------------------------------------------------------
// Launch
// ---------------------------------------------------------------------------
extern "C" void kernel_launch(void* const* d_in, const int* in_sizes, int n_in,
                              void* d_out, int out_size) {
    const float* features = (const float*)d_in[0];
    const int*   src      = (const int*)  d_in[1];
    const int*   dst      = (const int*)  d_in[2];
    const float* W1       = (const float*)d_in[3];
    const float* b1       = (const float*)d_in[4];
    const float* W2       = (const float*)d_in[5];
    const float* b2       = (const float*)d_in[6];
    const float* W3       = (const float*)d_in[7];
    const float* b3       = (const float*)d_in[8];
    float* out = (float*)d_out;

    __half *fa, *w1t, *x1, *w2t, *t1, *t2;
    float *x2;
    cudaGetSymbolAddress((void**)&fa, g_fa);
    cudaGetSymbolAddress((void**)&w1t, g_w1t);
    cudaGetSymbolAddress((void**)&x1, g_x1);
    cudaGetSymbolAddress((void**)&w2t, g_w2t);
    cudaGetSymbolAddress((void**)&t1, g_t1);
    cudaGetSymbolAddress((void**)&t2, g_t2);
    cudaGetSymbolAddress((void**)&x2, g_x2);

    cudaFuncSetAttribute(hmma_gemm_f16_kernel,
                         cudaFuncAttributeMaxDynamicSharedMemorySize, GEMM_SMEM);

    // CSR build
    zero_counts_kernel<<<(NNODES + 255) / 256, 256>>>();
    count_kernel<<<(NEDGES + 255) / 256, 256>>>(dst);
    scan_kernel<<<1, 1024>>>();
    fill_kernel<<<(NEDGES + 255) / 256, 256>>>(src, dst);

    // Conversions
    {
        size_t tot4 = (size_t)NNODES * (K1PAD / 4);
        quantize_pad_kernel<<<(unsigned)((tot4 + 255) / 256), 256>>>(
            features, fa, NNODES, D_IN, K1PAD);
        size_t wt = (size_t)N1PAD * K1PAD;
        transpose_f16_kernel<<<(unsigned)((wt + 255) / 256), 256>>>(
            W1, w1t, D_IN, D_H1, K1PAD, N1PAD);
        size_t wt2 = (size_t)N2PAD * K2PAD;
        transpose_f16_kernel<<<(unsigned)((wt2 + 255) / 256), 256>>>(
            W2, w2t, D_H1, D_H2, K2PAD, N2PAD);
    }

    // Layer 1: t1 = fa @ W1^T (fp16 out); x1 = relu(agg(t1)+b1) (fp16, padded)
    {
        dim3 grid(N1PAD / 128, (NNODES + 127) / 128);
        hmma_gemm_f16_kernel<<<grid, 256, GEMM_SMEM>>>(fa, w1t, t1,
                                                       NNODES, D_H1, K1PAD);
        agg1_kernel<<<NNODES, 256>>>(t1, b1, x1);
    }

    // Layer 2: t2 = x1 @ W2^T (fp16 out); x2 = relu(agg(t2)+b2) (fp32)
    {
        dim3 grid(N2PAD / 128, (NNODES + 127) / 128);
        hmma_gemm_f16_kernel<<<grid, 256, GEMM_SMEM>>>(x1, w2t, t2,
                                                       NNODES, D_H2, K2PAD);
        agg2_kernel<<<NNODES, 128>>>(t2, b2, x2);
    }

    // Output layer
    {
        int blocks = (NNODES + 7) / 8;
        out_layer_kernel<<<blocks, 256>>>(x2, W3, b3, out);
    }
}

// round 7
// speedup vs baseline: 6.4027x; 1.1784x over previous
#include <cuda_runtime.h>
#include <cuda_fp16.h>
#include <cstdint>

// Problem constants
#define NNODES 20000
#define NEDGES 200000
#define D_IN   1433
#define D_H1   1000
#define D_H2   500
#define D_OUT  7

// Padded GEMM dims
#define K1PAD  1472   // >= 1433, mult of 64
#define K2PAD  1024   // >= 1000, mult of 64
#define N1PAD  1024   // >= 1000, mult of 128
#define N2PAD  512    // >= 500,  mult of 128

// ---------------------------------------------------------------------------
// Device scratch
// ---------------------------------------------------------------------------
__device__ __align__(256) __half g_fa[(size_t)NNODES * K1PAD];    // fp16 features, padded
__device__ __align__(256) __half g_w1t[(size_t)N1PAD * K1PAD];    // W1^T fp16
__device__ __align__(256) __half g_x1[(size_t)NNODES * K2PAD];    // relu(agg(t1)+b1) fp16, padded
__device__ __align__(256) __half g_w2t[(size_t)N2PAD * K2PAD];    // W2^T fp16
__device__ __align__(256) __half g_t1[(size_t)NNODES * D_H1];     // features @ W1, fp16
__device__ __align__(256) __half g_t2[(size_t)NNODES * D_H2];     // x1 @ W2, fp16
__device__ __align__(256) float  g_x2[(size_t)NNODES * D_H2];     // relu(agg(t2)+b2) fp32
__device__ int g_count[NNODES];
__device__ int g_pos[NNODES];
__device__ int g_offs[NNODES + 1];
__device__ int g_eidx[NEDGES];

// ---------------------------------------------------------------------------
// PTX helpers (portable ISA: ldmatrix / mma.sync / cp.async)
// ---------------------------------------------------------------------------
__device__ __forceinline__ uint32_t smem_to_u32(const void* p) {
    uint32_t a;
    asm("{ .reg .u64 t; cvta.to.shared.u64 t, %1; cvt.u32.u64 %0, t; }"
        : "=r"(a) : "l"(p));
    return a;
}

__device__ __forceinline__ void cp_async16(uint32_t sdst, const void* gsrc, bool ok) {
    int sz = ok ? 16 : 0;
    asm volatile("cp.async.cg.shared.global [%0], [%1], 16, %2;\n"
                 :: "r"(sdst), "l"(gsrc), "r"(sz));
}
#define CP_COMMIT() asm volatile("cp.async.commit_group;\n" ::: "memory")
#define CP_WAIT(n)  asm volatile("cp.async.wait_group %0;\n" :: "n"(n) : "memory")

__device__ __forceinline__ void ldm_x4(uint32_t& r0, uint32_t& r1, uint32_t& r2,
                                       uint32_t& r3, uint32_t addr) {
    asm volatile("ldmatrix.sync.aligned.m8n8.x4.shared.b16 {%0,%1,%2,%3}, [%4];"
                 : "=r"(r0), "=r"(r1), "=r"(r2), "=r"(r3) : "r"(addr));
}

__device__ __forceinline__ void mma_f16(float* c, const uint32_t* a, const uint32_t* b) {
    asm volatile(
        "mma.sync.aligned.m16n8k16.row.col.f32.f16.f16.f32 "
        "{%0,%1,%2,%3}, {%4,%5,%6,%7}, {%8,%9}, {%0,%1,%2,%3};"
        : "+f"(c[0]), "+f"(c[1]), "+f"(c[2]), "+f"(c[3])
        : "r"(a[0]), "r"(a[1]), "r"(a[2]), "r"(a[3]), "r"(b[0]), "r"(b[1]));
}

__device__ __forceinline__ uint32_t pack_f16x2(float a, float b) {
    __half2 h = __floats2half2_rn(a, b);
    return *reinterpret_cast<uint32_t*>(&h);
}

struct __align__(8) half4 { __half2 a, b; };

// ---------------------------------------------------------------------------
// CSR build
// ---------------------------------------------------------------------------
__global__ void zero_counts_kernel() {
    int i = blockIdx.x * blockDim.x + threadIdx.x;
    if (i < NNODES) { g_count[i] = 0; g_pos[i] = 0; }
}
__global__ void count_kernel(const int* __restrict__ dst) {
    int e = blockIdx.x * blockDim.x + threadIdx.x;
    if (e < NEDGES) atomicAdd(&g_count[dst[e]], 1);
}
__global__ void scan_kernel() {
    __shared__ int part[1024];
    const int tid = threadIdx.x;
    const int CH = (NNODES + 1023) / 1024;
    const int base = tid * CH;
    int s = 0;
    for (int i = 0; i < CH; ++i) {
        int idx = base + i;
        if (idx < NNODES) s += g_count[idx];
    }
    part[tid] = s;
    __syncthreads();
    for (int off = 1; off < 1024; off <<= 1) {
        int v = (tid >= off) ? part[tid - off] : 0;
        __syncthreads();
        part[tid] += v;
        __syncthreads();
    }
    int run = part[tid] - s;
    for (int i = 0; i < CH; ++i) {
        int idx = base + i;
        if (idx < NNODES) { g_offs[idx] = run; run += g_count[idx]; }
    }
    if (tid == 1023) g_offs[NNODES] = part[1023];
}
__global__ void fill_kernel(const int* __restrict__ src, const int* __restrict__ dst) {
    int e = blockIdx.x * blockDim.x + threadIdx.x;
    if (e < NEDGES) {
        int d = dst[e];
        int p = atomicAdd(&g_pos[d], 1);
        g_eidx[g_offs[d] + p] = src[e];
    }
}

// ---------------------------------------------------------------------------
// Conversion: fp32 -> fp16, zero-padded; 4 elems/thread
// ---------------------------------------------------------------------------
__global__ void quantize_pad_kernel(const float* __restrict__ src,
                                    __half* __restrict__ dstq,
                                    int M, int K, int Kpad) {
    size_t idx4 = (size_t)blockIdx.x * blockDim.x + threadIdx.x;
    size_t total4 = (size_t)M * (Kpad >> 2);
    if (idx4 >= total4) return;
    int gpr = Kpad >> 2;
    int r = (int)(idx4 / gpr);
    int c = (int)(idx4 % gpr) << 2;
    float v[4];
#pragma unroll
    for (int j = 0; j < 4; ++j) {
        int cj = c + j;
        v[j] = (cj < K) ? src[(size_t)r * K + cj] : 0.f;
    }
    size_t o = (size_t)r * Kpad + c;
    *reinterpret_cast<uint2*>(dstq + o) =
        make_uint2(pack_f16x2(v[0], v[1]), pack_f16x2(v[2], v[3]));
}

// W [K,N] row-major -> Wt fp16 [Npad][Kpad] (K-major rows), zero-padded
__global__ void transpose_f16_kernel(const float* __restrict__ W,
                                     __half* __restrict__ t,
                                     int K, int N, int Kpad, int Npad) {
    size_t idx = (size_t)blockIdx.x * blockDim.x + threadIdx.x;
    size_t total = (size_t)Npad * Kpad;
    if (idx >= total) return;
    int n = (int)(idx / Kpad);
    int k = (int)(idx % Kpad);
    float x = (n < N && k < K) ? W[(size_t)k * N + n] : 0.f;
    t[idx] = __float2half(x);
}

// ---------------------------------------------------------------------------
// HMMA GEMM, 3-stage cp.async pipeline, BK=64, occupancy 2:
//   C[M, Nreal](fp16) = A@B^T   (fp32 accum; A, B fp16)
// CTA tile 128x128, 8 warps (4m x 2n), warp tile 32x64, 2 CTAs/SM.
// SMEM rows padded to 72 halves (conflict-free ldmatrix).
// ---------------------------------------------------------------------------
#define BK 64
#define ROW_H 72                                // halves per smem row (64 + 8)
#define MAT_BYTES ((uint32_t)(128 * ROW_H * 2)) // 18432
#define B_OFF     MAT_BYTES
#define STAGE_BYTES (2 * MAT_BYTES)             // 36864
#define NSTAGE 3
#define GEMM_SMEM (NSTAGE * STAGE_BYTES)        // 110592

__global__ __launch_bounds__(256, 2)
void hmma_gemm_f16_kernel(const __half* __restrict__ a,
                          const __half* __restrict__ b,
                          __half* __restrict__ C,
                          int M, int Nreal, int Kpad) {
    extern __shared__ __half smem[];
    const uint32_t smem_u32 = smem_to_u32(smem);
    const int t = threadIdx.x;
    const int lane = t & 31;
    const int wid = t >> 5;
    const int wm = wid & 3;
    const int wn = wid >> 2;
    const int m0 = blockIdx.y * 128;
    const int n0 = blockIdx.x * 128;
    const int nchunk = Kpad / BK;

    float acc[2][8][4];
#pragma unroll
    for (int i = 0; i < 2; ++i)
#pragma unroll
        for (int j = 0; j < 8; ++j)
#pragma unroll
            for (int k = 0; k < 4; ++k) acc[i][j][k] = 0.f;

    auto load_stage = [&](int c) {
        const int slot = c % NSTAGE;
        const int k0 = c * BK;
        const uint32_t sbase = smem_u32 + slot * STAGE_BYTES;
#pragma unroll
        for (int i = 0; i < 4; ++i) {
            int idx = t + i * 256;          // 0..1023
            int row = idx >> 3;             // 0..127
            int ch = idx & 7;               // 16B chunk within 128B row
            uint32_t off = (uint32_t)(row * ROW_H + ch * 8) * 2;
            int gm = m0 + row;
            bool ok = gm < M;
            int gmc = ok ? gm : 0;
            size_t goa = (size_t)gmc * Kpad + k0 + ch * 8;
            cp_async16(sbase + off, a + goa, ok);
            size_t gob = (size_t)(n0 + row) * Kpad + k0 + ch * 8;
            cp_async16(sbase + off + B_OFF, b + gob, true);
        }
        CP_COMMIT();
    };

    // prologue: two stages in flight
    load_stage(0);
    if (nchunk > 1) load_stage(1);

    for (int c = 0; c < nchunk; ++c) {
        if (c + 1 < nchunk) { CP_WAIT(1); } else { CP_WAIT(0); }
        __syncthreads();   // stage c ready; all warps done with compute(c-1)
        if (c + 2 < nchunk) load_stage(c + 2);

        const uint32_t sb = smem_u32 + (uint32_t)(c % NSTAGE) * STAGE_BYTES;
#pragma unroll
        for (int ks = 0; ks < 4; ++ks) {
            const int k0s = ks * 16;
            uint32_t af[2][4];
            {
                int ar = lane & 15;
                int ak = k0s + (lane >> 4) * 8;
#pragma unroll
                for (int mt = 0; mt < 2; ++mt) {
                    uint32_t addr = sb +
                        (uint32_t)((wm * 32 + mt * 16 + ar) * ROW_H + ak) * 2;
                    ldm_x4(af[mt][0], af[mt][1], af[mt][2], af[mt][3], addr);
                }
            }
            uint32_t bf[8][2];
            {
                int brr = (lane & 7) + (lane >> 4) * 8;
                int bk = k0s + ((lane >> 3) & 1) * 8;
#pragma unroll
                for (int ng = 0; ng < 4; ++ng) {
                    uint32_t addr = sb + B_OFF +
                        (uint32_t)((wn * 64 + ng * 16 + brr) * ROW_H + bk) * 2;
                    uint32_t r0, r1, r2, r3;
                    ldm_x4(r0, r1, r2, r3, addr);
                    bf[2 * ng][0] = r0; bf[2 * ng][1] = r1;
                    bf[2 * ng + 1][0] = r2; bf[2 * ng + 1][1] = r3;
                }
            }
#pragma unroll
            for (int mt = 0; mt < 2; ++mt) {
#pragma unroll
                for (int nt = 0; nt < 8; ++nt) {
                    mma_f16(acc[mt][nt], af[mt], bf[nt]);
                }
            }
        }
    }

    // epilogue: fp16 packed stores (pairs of columns)
#pragma unroll
    for (int mt = 0; mt < 2; ++mt) {
        int gr0 = m0 + wm * 32 + mt * 16 + (lane >> 2);
#pragma unroll
        for (int nt = 0; nt < 8; ++nt) {
            int gc = n0 + wn * 64 + nt * 8 + (lane & 3) * 2;
            if (gc >= Nreal) continue;   // Nreal even -> pair never straddles
            if (gr0 < M) {
                *reinterpret_cast<uint32_t*>(&C[(size_t)gr0 * Nreal + gc]) =
                    pack_f16x2(acc[mt][nt][0], acc[mt][nt][1]);
            }
            if (gr0 + 8 < M) {
                *reinterpret_cast<uint32_t*>(&C[(size_t)(gr0 + 8) * Nreal + gc]) =
                    pack_f16x2(acc[mt][nt][2], acc[mt][nt][3]);
            }
        }
    }
}

// ---------------------------------------------------------------------------
// Aggregation 1: x1[i,:] = relu(b1 + sum_j t1[j,:]) -> fp16, padded to K2PAD
// 128 threads/node, 8 halves (16B) per thread; fp32 accumulation.
// ---------------------------------------------------------------------------
__global__ __launch_bounds__(128)
void agg1_kernel(const __half* __restrict__ t,
                 const float* __restrict__ bias,
                 __half* __restrict__ x1) {
    __shared__ int nbr[512];
    const int node = blockIdx.x;
    const int beg = g_offs[node], end = g_offs[node + 1];
    const int deg = end - beg;
    const int* elist;
    if (deg <= 512) {
        for (int i = threadIdx.x; i < deg; i += blockDim.x) nbr[i] = g_eidx[beg + i];
        __syncthreads();
        elist = nbr;
    } else {
        elist = g_eidx + beg;
    }
    const int c = threadIdx.x << 3;       // 0..1016
    if (c < D_H1) {                       // threads 0..124 (1000 = 125*8)
        float a[8];
#pragma unroll
        for (int j = 0; j < 8; ++j) a[j] = bias[c + j];
        for (int e = 0; e < deg; ++e) {
            const uint4 v = *reinterpret_cast<const uint4*>(
                t + (size_t)elist[e] * D_H1 + c);
            const __half2* h = reinterpret_cast<const __half2*>(&v);
#pragma unroll
            for (int j = 0; j < 4; ++j) {
                float2 p = __half22float2(h[j]);
                a[2 * j] += p.x;
                a[2 * j + 1] += p.y;
            }
        }
        uint4 o;
        uint32_t* ow = reinterpret_cast<uint32_t*>(&o);
#pragma unroll
        for (int j = 0; j < 4; ++j)
            ow[j] = pack_f16x2(fmaxf(a[2 * j], 0.f), fmaxf(a[2 * j + 1], 0.f));
        *reinterpret_cast<uint4*>(x1 + (size_t)node * K2PAD + c) = o;
    } else {
        // zero the K padding region (GEMM-A operand must be 0 there)
        *reinterpret_cast<uint4*>(x1 + (size_t)node * K2PAD + c) =
            make_uint4(0u, 0u, 0u, 0u);
    }
}

// Aggregation 2: x2[i,:] = relu(b2 + sum_j t2[j,:]) -> fp32. 128 thr/node.
__global__ __launch_bounds__(128)
void agg2_kernel(const __half* __restrict__ t,
                 const float* __restrict__ bias,
                 float* __restrict__ out) {
    __shared__ int nbr[512];
    const int node = blockIdx.x;
    const int beg = g_offs[node], end = g_offs[node + 1];
    const int deg = end - beg;
    const int* elist;
    if (deg <= 512) {
        for (int i = threadIdx.x; i < deg; i += blockDim.x) nbr[i] = g_eidx[beg + i];
        __syncthreads();
        elist = nbr;
    } else {
        elist = g_eidx + beg;
    }
    const int c = threadIdx.x << 2;
    if (c >= D_H2) return;     // D_H2 = 500 -> 125 groups
    float a0 = bias[c], a1 = bias[c + 1], a2 = bias[c + 2], a3 = bias[c + 3];
    for (int e = 0; e < deg; ++e) {
        const half4 v = *reinterpret_cast<const half4*>(
            t + (size_t)elist[e] * D_H2 + c);
        float2 p = __half22float2(v.a);
        float2 q = __half22float2(v.b);
        a0 += p.x; a1 += p.y; a2 += q.x; a3 += q.y;
    }
    float4 r = make_float4(fmaxf(a0, 0.f), fmaxf(a1, 0.f),
                           fmaxf(a2, 0.f), fmaxf(a3, 0.f));
    *reinterpret_cast<float4*>(out + (size_t)node * D_H2 + c) = r;
}

// ---------------------------------------------------------------------------
// Output layer: out[i,:7] = relu(x2[i,:] @ W3 + b3), one warp per row
// ---------------------------------------------------------------------------
__global__ void out_layer_kernel(const float* __restrict__ x2,
                                 const float* __restrict__ W3,
                                 const float* __restrict__ b3,
                                 float* __restrict__ out) {
    __shared__ float Ws[D_H2 * D_OUT];
    for (int i = threadIdx.x; i < D_H2 * D_OUT; i += blockDim.x) Ws[i] = W3[i];
    __syncthreads();
    const int warp = (blockIdx.x * blockDim.x + threadIdx.x) >> 5;
    const int lane = threadIdx.x & 31;
    if (warp >= NNODES) return;
    float acc[D_OUT] = {0.f, 0.f, 0.f, 0.f, 0.f, 0.f, 0.f};
    const float* row = x2 + (size_t)warp * D_H2;
    for (int k = lane; k < D_H2; k += 32) {
        float v = row[k];
#pragma unroll
        for (int j = 0; j < D_OUT; ++j) acc[j] += v * Ws[k * D_OUT + j];
    }
#pragma unroll
    for (int j = 0; j < D_OUT; ++j) {
#pragma unroll
        for (int off = 16; off > 0; off >>= 1)
            acc[j] += __shfl_xor_sync(0xFFFFFFFFu, acc[j], off);
    }
    if (lane == 0) {
#pragma unroll
        for (int j = 0; j < D_OUT; ++j)
            out[(size_t)warp * D_OUT + j] = fmaxf(acc[j] + b3[j], 0.f);
    }
}

// ---------------------------------------------------------------------------
// Launch — conversions + gemm1 first (gemm1 lands on the ncu capture slot),
// CSR build after (agg1 is the first consumer of the CSR).
// ---------------------------------------------------------------------------
extern "C" void kernel_launch(void* const* d_in, const int* in_sizes, int n_in,
                              void* d_out, int out_size) {
    const float* features = (const float*)d_in[0];
    const int*   src      = (const int*)  d_in[1];
    const int*   dst      = (const int*)  d_in[2];
    const float* W1       = (const float*)d_in[3];
    const float* b1       = (const float*)d_in[4];
    const float* W2       = (const float*)d_in[5];
    const float* b2       = (const float*)d_in[6];
    const float* W3       = (const float*)d_in[7];
    const float* b3       = (const float*)d_in[8];
    float* out = (float*)d_out;

    __half *fa, *w1t, *x1, *w2t, *t1, *t2;
    float *x2;
    cudaGetSymbolAddress((void**)&fa, g_fa);
    cudaGetSymbolAddress((void**)&w1t, g_w1t);
    cudaGetSymbolAddress((void**)&x1, g_x1);
    cudaGetSymbolAddress((void**)&w2t, g_w2t);
    cudaGetSymbolAddress((void**)&t1, g_t1);
    cudaGetSymbolAddress((void**)&t2, g_t2);
    cudaGetSymbolAddress((void**)&x2, g_x2);

    cudaFuncSetAttribute(hmma_gemm_f16_kernel,
                         cudaFuncAttributeMaxDynamicSharedMemorySize, GEMM_SMEM);

    // Conversions (launches 0-2)
    {
        size_t tot4 = (size_t)NNODES * (K1PAD / 4);
        quantize_pad_kernel<<<(unsigned)((tot4 + 255) / 256), 256>>>(
            features, fa, NNODES, D_IN, K1PAD);
        size_t wt = (size_t)N1PAD * K1PAD;
        transpose_f16_kernel<<<(unsigned)((wt + 255) / 256), 256>>>(
            W1, w1t, D_IN, D_H1, K1PAD, N1PAD);
        size_t wt2 = (size_t)N2PAD * K2PAD;
        transpose_f16_kernel<<<(unsigned)((wt2 + 255) / 256), 256>>>(
            W2, w2t, D_H1, D_H2, K2PAD, N2PAD);
    }

    // GEMM 1 (launch 3 — ncu capture slot): t1 = fa @ W1^T (fp16 out)
    {
        dim3 grid(N1PAD / 128, (NNODES + 127) / 128);
        hmma_gemm_f16_kernel<<<grid, 256, GEMM_SMEM>>>(fa, w1t, t1,
                                                       NNODES, D_H1, K1PAD);
    }

    // CSR build (launches 4-7) — only needed from agg1 onward
    zero_counts_kernel<<<(NNODES + 255) / 256, 256>>>();
    count_kernel<<<(NEDGES + 255) / 256, 256>>>(dst);
    scan_kernel<<<1, 1024>>>();
    fill_kernel<<<(NEDGES + 255) / 256, 256>>>(src, dst);

    // Layer 1 aggregation: x1 = relu(agg(t1)+b1) (fp16, padded)
    agg1_kernel<<<NNODES, 128>>>(t1, b1, x1);

    // Layer 2: t2 = x1 @ W2^T (fp16 out); x2 = relu(agg(t2)+b2) (fp32)
    {
        dim3 grid(N2PAD / 128, (NNODES + 127) / 128);
        hmma_gemm_f16_kernel<<<grid, 256, GEMM_SMEM>>>(x1, w2t, t2,
                                                       NNODES, D_H2, K2PAD);
        agg2_kernel<<<NNODES, 128>>>(t2, b2, x2);
    }

    // Output layer
    {
        int blocks = (NNODES + 7) / 8;
        out_layer_kernel<<<blocks, 256>>>(x2, W3, b3, out);
    }
}